// round 13
// baseline (speedup 1.0000x reference)
#include <cuda_runtime.h>
#include <math.h>

typedef unsigned long long ull;

namespace {
constexpr int NSEQ = 512;
constexpr int LRES = 1024;
constexpr int NT   = 1024;
constexpr int KVS  = 516;   // kT/vT padded stride (conflict-free col stores)
constexpr float LN_EPS = 1e-5f;

struct __align__(16) Smem {
    float xg[64 * NSEQ];      // 128 KB: X transposed+swizzled, then G in place
    float wc[64][80];         // 20 KB: cols 0-63 Wg, 64-71 Wk, 72-79 Wv
    float wo[64 * 64];        // 16 KB (ovec-folded before pass B)
    float kT[8 * KVS];        // k transposed (padded)
    float vT[8 * KVS];        // v transposed (padded)
    float lnw[64], lnb[64], bgv[64], bov[64], xsum[64], qvec[64], ovec[64];
    float xpart[16 * 64];     // 4 KB
    float mpart[32], spart[32], opart[32][8];
};  // ~202 KB

__device__ __forceinline__ int swz(int c) { return ((c >> 3) ^ c) & 7; }
__device__ __forceinline__ void ffma2(ull& d_, ull a, ull b) {
    asm("fma.rn.f32x2 %0, %1, %2, %0;" : "+l"(d_) : "l"(a), "l"(b));
}
__device__ __forceinline__ ull splat2(float x) {
    ull r; asm("mov.b64 %0, {%1, %1};" : "=l"(r) : "f"(x)); return r;
}
__device__ __forceinline__ ull add2(ull a, ull b) {
    ull r; asm("add.rn.f32x2 %0, %1, %2;" : "=l"(r) : "l"(a), "l"(b)); return r;
}
__device__ __forceinline__ void unpack2(ull u, float& lo, float& hi) {
    asm("mov.b64 {%0, %1}, %2;" : "=f"(lo), "=f"(hi) : "l"(u));
}
// sigmoid(x) = 0.5*tanh(x/2) + 0.5  (single MUFU)
__device__ __forceinline__ float sigmoid_t(float v) {
    float t; asm("tanh.approx.f32 %0, %1;" : "=f"(t) : "f"(v * 0.5f));
    return fmaf(t, 0.5f, 0.5f);
}
} // namespace

__global__ void __launch_bounds__(NT, 1)
msa_col_attn_v13(const float* __restrict__ msa,
                 const float* __restrict__ g_lnw, const float* __restrict__ g_lnb,
                 const float* __restrict__ g_wq,  const float* __restrict__ g_wk,
                 const float* __restrict__ g_wv,  const float* __restrict__ g_wg,
                 const float* __restrict__ g_bg,  const float* __restrict__ g_wo,
                 const float* __restrict__ g_bo,  float* __restrict__ out)
{
    extern __shared__ float smf[];
    Smem* s = reinterpret_cast<Smem*>(smf);
    const int tid  = threadIdx.x;
    const int l    = blockIdx.x;
    const int lane = tid & 31;
    const int wid  = tid >> 5;

    // ---------------- preamble: weights to SMEM ----------------
    {
        int d = tid >> 4, c4 = (tid & 15) * 4;
        *reinterpret_cast<float4*>(&s->wc[d][c4]) =
            *reinterpret_cast<const float4*>(g_wg + d * 64 + c4);
        if (tid < 512) {
            int dd = tid >> 3, j = tid & 7;
            s->wc[dd][64 + j] = g_wk[tid];
            s->wc[dd][72 + j] = g_wv[tid];
        }
        ((float4*)s->wo)[tid] = ((const float4*)g_wo)[tid];
        if (tid < 64) {
            s->lnw[tid] = g_lnw[tid];
            s->lnb[tid] = g_lnb[tid];
            s->bgv[tid] = g_bg[tid];
            s->bov[tid] = g_bo[tid];
        }
    }
    // wq in registers: thread (dg = tid>>6, c = tid&63) holds wq[4dg+i][c]
    float wqr[4];
    {
        int dg = tid >> 6, c = tid & 63;
        #pragma unroll
        for (int i = 0; i < 4; ++i) wqr[i] = g_wq[(4 * dg + i) * 64 + c];
    }
    __syncthreads();

    // ---------------- LayerNorm: 512x64 -> xg transposed+swizzled ----------------
    // 2 threads per row (conflict-free stores: half-parity flips swz by ^4)
    {
        const int lrow  = tid >> 1;     // 0..511
        const int lhalf = tid & 1;      // cols 32*lhalf .. +31
        const float* src = msa + ((size_t)lrow * LRES + l) * 64 + lhalf * 32;
        float4 r[8];
        #pragma unroll
        for (int j = 0; j < 8; ++j) r[j] = ((const float4*)src)[j];

        float sm = 0.f, sq = 0.f;
        #pragma unroll
        for (int j = 0; j < 8; ++j) {
            float4 t = r[j];
            sm += (t.x + t.y) + (t.z + t.w);
            sq  = fmaf(t.x, t.x, fmaf(t.y, t.y, fmaf(t.z, t.z, fmaf(t.w, t.w, sq))));
        }
        sm += __shfl_xor_sync(0xffffffffu, sm, 1);
        sq += __shfl_xor_sync(0xffffffffu, sq, 1);
        float mu   = sm * (1.f / 64.f);
        float var  = sq * (1.f / 64.f) - mu * mu;
        float rstd = rsqrtf(var + LN_EPS);
        float mrs  = -mu * rstd;
        const int rb = lrow >> 2, r0 = lrow & 3;
        #pragma unroll
        for (int j = 0; j < 8; ++j) {
            float4 t = r[j];
            int c0 = lhalf * 32 + 4 * j;
            s->xg[(c0 + 0) * NSEQ + 4 * (rb ^ swz(c0 + 0)) + r0] =
                fmaf(fmaf(t.x, rstd, mrs), s->lnw[c0 + 0], s->lnb[c0 + 0]);
            s->xg[(c0 + 1) * NSEQ + 4 * (rb ^ swz(c0 + 1)) + r0] =
                fmaf(fmaf(t.y, rstd, mrs), s->lnw[c0 + 1], s->lnb[c0 + 1]);
            s->xg[(c0 + 2) * NSEQ + 4 * (rb ^ swz(c0 + 2)) + r0] =
                fmaf(fmaf(t.z, rstd, mrs), s->lnw[c0 + 2], s->lnb[c0 + 2]);
            s->xg[(c0 + 3) * NSEQ + 4 * (rb ^ swz(c0 + 3)) + r0] =
                fmaf(fmaf(t.w, rstd, mrs), s->lnw[c0 + 3], s->lnb[c0 + 3]);
        }
    }
    __syncthreads();

    // ---------------- xsum partials: lane-rotated scalar reads (conflict-free) ----------------
    {
        const int seg = tid >> 6, c = tid & 63;   // 16 segs x 32 rows
        const float* colp = s->xg + c * NSEQ + seg * 32;
        float t0 = 0.f, t1 = 0.f, t2 = 0.f, t3 = 0.f;
        #pragma unroll
        for (int j = 0; j < 32; j += 4) {
            t0 += colp[(lane + j + 0) & 31];
            t1 += colp[(lane + j + 1) & 31];
            t2 += colp[(lane + j + 2) & 31];
            t3 += colp[(lane + j + 3) & 31];
        }
        s->xpart[seg * 64 + c] = (t0 + t1) + (t2 + t3);
    }
    __syncthreads();

    // xsum reduce (GEMM below doesn't touch xsum; consumers are after the next barrier)
    if (tid < 64) {
        float t = 0.f;
        #pragma unroll
        for (int w = 0; w < 16; ++w) t += s->xpart[w * 64 + tid];
        s->xsum[tid] = t;
    }

    // ---------------- pass A: fused gate + kv GEMM (4 rows x 8 cols + kv pair) ----------------
    const int rg = tid >> 3;    // row-block (rows 4rg..4rg+3), 0..127
    const int cg = tid & 7;     // gate cols 8cg..8cg+7; kv cols 2cg,2cg+1
    ull ga[4][4];
    ull ka[4];
    #pragma unroll
    for (int p = 0; p < 4; ++p) {
        ka[p] = 0;
        #pragma unroll
        for (int q = 0; q < 4; ++q) ga[p][q] = 0;
    }
    #pragma unroll 1
    for (int a = 0; a < 8; ++a) {
        const float* xcol  = s->xg + a * 8 * NSEQ;
        const int ea = (rg ^ a) << 2;
        const float* wg_p  = &s->wc[a * 8][8 * cg];
        const float* wkv_p = &s->wc[a * 8][64 + 2 * cg];
        #pragma unroll
        for (int b = 0; b < 8; ++b) {
            float4 xa = *reinterpret_cast<const float4*>(xcol + b * NSEQ + (ea ^ (b << 2)));
            ulonglong2 w0 = *reinterpret_cast<const ulonglong2*>(wg_p + b * 80);
            ulonglong2 w1 = *reinterpret_cast<const ulonglong2*>(wg_p + b * 80 + 4);
            ull wk = *reinterpret_cast<const ull*>(wkv_p + b * 80);
            ull t;
            t = splat2(xa.x); ffma2(ga[0][0],t,w0.x); ffma2(ga[0][1],t,w0.y); ffma2(ga[0][2],t,w1.x); ffma2(ga[0][3],t,w1.y); ffma2(ka[0],t,wk);
            t = splat2(xa.y); ffma2(ga[1][0],t,w0.x); ffma2(ga[1][1],t,w0.y); ffma2(ga[1][2],t,w1.x); ffma2(ga[1][3],t,w1.y); ffma2(ka[1],t,wk);
            t = splat2(xa.z); ffma2(ga[2][0],t,w0.x); ffma2(ga[2][1],t,w0.y); ffma2(ga[2][2],t,w1.x); ffma2(ga[2][3],t,w1.y); ffma2(ka[2],t,wk);
            t = splat2(xa.w); ffma2(ga[3][0],t,w0.x); ffma2(ga[3][1],t,w0.y); ffma2(ga[3][2],t,w1.x); ffma2(ga[3][3],t,w1.y); ffma2(ka[3],t,wk);
        }
    }
    __syncthreads();   // all xg reads done; safe to overwrite with G

    // gate epilogue: G = sigmoid(P + bg) -> xg (same layout)
    #pragma unroll
    for (int c = 0; c < 8; ++c) {
        int col = 8 * cg + c;
        float bgc = s->bgv[col];
        float g[4];
        #pragma unroll
        for (int p = 0; p < 4; ++p) {
            float lo, hi;
            unpack2(ga[p][c >> 1], lo, hi);
            g[p] = sigmoid_t(((c & 1) ? hi : lo) + bgc);
        }
        *reinterpret_cast<float4*>(&s->xg[col * NSEQ + 4 * (rg ^ swz(col))]) =
            make_float4(g[0], g[1], g[2], g[3]);
    }
    // kv epilogue -> kT / vT (transposed, padded stride)
    #pragma unroll
    for (int cc = 0; cc < 2; ++cc) {
        int gcol = 2 * cg + cc;      // 0-7 = k col, 8-15 = v col
        float k4[4];
        #pragma unroll
        for (int p = 0; p < 4; ++p) {
            float lo, hi;
            unpack2(ka[p], lo, hi);
            k4[p] = cc ? hi : lo;
        }
        float* dst = (gcol < 8) ? (s->kT + gcol * KVS) : (s->vT + (gcol - 8) * KVS);
        *reinterpret_cast<float4*>(dst + 4 * rg) = make_float4(k4[0], k4[1], k4[2], k4[3]);
    }
    // qvec partials (xsum written before previous barrier)
    {
        int dg = tid >> 6, c = tid & 63;
        float p = 0.f;
        #pragma unroll
        for (int i = 0; i < 4; ++i) p = fmaf(s->xsum[4 * dg + i], wqr[i], p);
        s->xpart[dg * 64 + c] = p;
    }
    __syncthreads();

    if (tid < 64) {
        float q = 0.f;
        #pragma unroll
        for (int dg = 0; dg < 16; ++dg) q += s->xpart[dg * 64 + tid];
        s->qvec[tid] = q * (float)(0.35355339059327373 / 512.0); // (1/sqrt(8))/N
    }
    __syncthreads();

    // ---------------- softmax with inline scores: 4 warps per head ----------------
    {
        int h = wid >> 2, q4 = wid & 3;
        const float* qf = s->qvec + 8 * h;
        float q0 = qf[0], q1 = qf[1], q2 = qf[2], q3 = qf[3];
        float q4v = qf[4], q5 = qf[5], q6 = qf[6], q7 = qf[7];
        float sv[4], m = -1e30f;
        #pragma unroll
        for (int j = 0; j < 4; ++j) {
            int n = q4 * 128 + lane + 32 * j;
            float sc = q0 * s->kT[0 * KVS + n] + q1 * s->kT[1 * KVS + n]
                     + q2 * s->kT[2 * KVS + n] + q3 * s->kT[3 * KVS + n]
                     + q4v * s->kT[4 * KVS + n] + q5 * s->kT[5 * KVS + n]
                     + q6 * s->kT[6 * KVS + n] + q7 * s->kT[7 * KVS + n];
            sv[j] = sc;
            m = fmaxf(m, sc);
        }
        #pragma unroll
        for (int off = 16; off > 0; off >>= 1)
            m = fmaxf(m, __shfl_xor_sync(0xffffffffu, m, off));
        float ssum = 0.f, acc[8];
        #pragma unroll
        for (int d = 0; d < 8; ++d) acc[d] = 0.f;
        #pragma unroll
        for (int j = 0; j < 4; ++j) {
            float e = __expf(sv[j] - m);
            ssum += e;
            int n = q4 * 128 + lane + 32 * j;
            #pragma unroll
            for (int d = 0; d < 8; ++d) acc[d] = fmaf(e, s->vT[d * KVS + n], acc[d]);
        }
        #pragma unroll
        for (int off = 16; off > 0; off >>= 1) {
            ssum += __shfl_xor_sync(0xffffffffu, ssum, off);
            #pragma unroll
            for (int d = 0; d < 8; ++d) acc[d] += __shfl_xor_sync(0xffffffffu, acc[d], off);
        }
        if (lane == 0) {
            s->mpart[wid] = m;
            s->spart[wid] = ssum;
            #pragma unroll
            for (int d = 0; d < 8; ++d) s->opart[wid][d] = acc[d];
        }
    }
    __syncthreads();

    // ovec combine (exact four-way softmax merge)
    if (tid < 64) {
        int h = tid >> 3, d = tid & 7;
        float m = -1e30f;
        #pragma unroll
        for (int q = 0; q < 4; ++q) m = fmaxf(m, s->mpart[4 * h + q]);
        float ss = 0.f, ov = 0.f;
        #pragma unroll
        for (int q = 0; q < 4; ++q) {
            float e = __expf(s->mpart[4 * h + q] - m);
            ss = fmaf(s->spart[4 * h + q], e, ss);
            ov = fmaf(s->opart[4 * h + q][d], e, ov);
        }
        s->ovec[8 * h + d] = ov / ss;
    }
    __syncthreads();

    // fold ovec into Wo rows (1 float4 per thread)
    {
        float4 w4 = ((float4*)s->wo)[tid];
        float ov = s->ovec[tid >> 4];
        w4.x *= ov; w4.y *= ov; w4.z *= ov; w4.w *= ov;
        ((float4*)s->wo)[tid] = w4;
    }
    __syncthreads();

    // ---------------- pass B: out = G @ Wo' + bo ----------------
    {
        ull acc[4][4];
        #pragma unroll
        for (int p = 0; p < 4; ++p)
            #pragma unroll
            for (int q = 0; q < 4; ++q) acc[p][q] = 0;

        #pragma unroll 1
        for (int a = 0; a < 8; ++a) {
            const float* gcol = s->xg + a * 8 * NSEQ;
            const int ea = (rg ^ a) << 2;
            const float* wo_p = s->wo + (a * 8) * 64 + 8 * cg;
            #pragma unroll
            for (int b = 0; b < 8; ++b) {
                float4 xa = *reinterpret_cast<const float4*>(gcol + b * NSEQ + (ea ^ (b << 2)));
                ulonglong2 wA = *reinterpret_cast<const ulonglong2*>(wo_p + b * 64);
                ulonglong2 wB = *reinterpret_cast<const ulonglong2*>(wo_p + b * 64 + 4);
                ull t;
                t = splat2(xa.x); ffma2(acc[0][0],t,wA.x); ffma2(acc[0][1],t,wA.y); ffma2(acc[0][2],t,wB.x); ffma2(acc[0][3],t,wB.y);
                t = splat2(xa.y); ffma2(acc[1][0],t,wA.x); ffma2(acc[1][1],t,wA.y); ffma2(acc[1][2],t,wB.x); ffma2(acc[1][3],t,wB.y);
                t = splat2(xa.z); ffma2(acc[2][0],t,wA.x); ffma2(acc[2][1],t,wA.y); ffma2(acc[2][2],t,wB.x); ffma2(acc[2][3],t,wB.y);
                t = splat2(xa.w); ffma2(acc[3][0],t,wA.x); ffma2(acc[3][1],t,wA.y); ffma2(acc[3][2],t,wB.x); ffma2(acc[3][3],t,wB.y);
            }
        }

        const ulonglong2 boA = *reinterpret_cast<const ulonglong2*>(&s->bov[8 * cg]);
        const ulonglong2 boB = *reinterpret_cast<const ulonglong2*>(&s->bov[8 * cg + 4]);
        #pragma unroll
        for (int p = 0; p < 4; ++p) {
            float* op = out + ((size_t)(4 * rg + p) * LRES + l) * 64 + 8 * cg;
            ulonglong2 v0, v1;
            v0.x = add2(acc[p][0], boA.x); v0.y = add2(acc[p][1], boA.y);
            v1.x = add2(acc[p][2], boB.x); v1.y = add2(acc[p][3], boB.y);
            *reinterpret_cast<ulonglong2*>(op)     = v0;
            *reinterpret_cast<ulonglong2*>(op + 4) = v1;
        }
    }
}

extern "C" void kernel_launch(void* const* d_in, const int* in_sizes, int n_in,
                              void* d_out, int out_size) {
    const float* msa = (const float*)d_in[0];
    const float* lnw = (const float*)d_in[1];
    const float* lnb = (const float*)d_in[2];
    const float* wq  = (const float*)d_in[3];
    const float* wk  = (const float*)d_in[4];
    const float* wv  = (const float*)d_in[5];
    const float* wg  = (const float*)d_in[6];
    const float* bg  = (const float*)d_in[7];
    const float* wo  = (const float*)d_in[8];
    const float* bo  = (const float*)d_in[9];
    float* out = (float*)d_out;

    const int smem_bytes = (int)sizeof(Smem);
    cudaFuncSetAttribute(msa_col_attn_v13,
                         cudaFuncAttributeMaxDynamicSharedMemorySize, smem_bytes);
    msa_col_attn_v13<<<LRES, NT, smem_bytes>>>(
        msa, lnw, lnb, wq, wk, wv, wg, bg, wo, bo, out);
}

// round 14
// speedup vs baseline: 1.3014x; 1.3014x over previous
#include <cuda_runtime.h>
#include <math.h>

typedef unsigned long long ull;

namespace {
constexpr int NSEQ = 512;
constexpr int LRES = 1024;
constexpr int NT   = 512;
constexpr float LN_EPS = 1e-5f;

struct __align__(16) Smem {
    float xg[64 * NSEQ];       // 128 KB: X transposed+swizzled, then G in place
    float wc[64][80];          // 20 KB: cols 0-63 Wg, 64-71 Wk, 72-79 Wv
    float wo[64 * 64];         // 16 KB, pristine (fold goes to scores area)
    float kbuf[NSEQ][8];       // 16 KB
    float vT[8 * NSEQ];        // 16 KB
    float scores[8 * NSEQ];    // 16 KB: scores; later holds ovec-folded Wo (4096 floats)
    float lnw[64], lnb[64], bgv[64], bov[64], xsum[64], qvec[64], ovec[64];
    float xpart[16 * 64];      // 4 KB
    float mpart[16], spart[16], opart[16][8];
};

__device__ __forceinline__ int swz(int c) { return ((c >> 3) ^ c) & 7; }
__device__ __forceinline__ void ffma2(ull& d_, ull a, ull b) {
    asm("fma.rn.f32x2 %0, %1, %2, %0;" : "+l"(d_) : "l"(a), "l"(b));
}
__device__ __forceinline__ ull splat2(float x) {
    ull r; asm("mov.b64 %0, {%1, %1};" : "=l"(r) : "f"(x)); return r;
}
__device__ __forceinline__ ull add2(ull a, ull b) {
    ull r; asm("add.rn.f32x2 %0, %1, %2;" : "=l"(r) : "l"(a), "l"(b)); return r;
}
__device__ __forceinline__ void unpack2(ull u, float& lo, float& hi) {
    asm("mov.b64 {%0, %1}, %2;" : "=f"(lo), "=f"(hi) : "l"(u));
}
// sigmoid(x) = 0.5*tanh(x/2) + 0.5  (single MUFU)
__device__ __forceinline__ float sigmoid_t(float v) {
    float t; asm("tanh.approx.f32 %0, %1;" : "=f"(t) : "f"(v * 0.5f));
    return fmaf(t, 0.5f, 0.5f);
}
} // namespace

__global__ void __launch_bounds__(NT, 1)
msa_col_attn_v14(const float* __restrict__ msa,
                 const float* __restrict__ g_lnw, const float* __restrict__ g_lnb,
                 const float* __restrict__ g_wq,  const float* __restrict__ g_wk,
                 const float* __restrict__ g_wv,  const float* __restrict__ g_wg,
                 const float* __restrict__ g_bg,  const float* __restrict__ g_wo,
                 const float* __restrict__ g_bo,  float* __restrict__ out)
{
    extern __shared__ float smf[];
    Smem* s = reinterpret_cast<Smem*>(smf);
    const int tid  = threadIdx.x;
    const int lane = tid & 31;
    const int wid  = tid >> 5;
    const int rg = tid >> 3;   // rows 8rg..8rg+7
    const int cg = tid & 7;    // cols 8cg..8cg+7

    // LN thread geometry (warp covers 2 rows/iter; 16 lanes span one 256B row)
    const int lq4 = lane & 15;
    const int lh  = lane >> 4;
    const size_t lnstep = (size_t)32 * LRES * 64;

    // early prefetch for column 0 (overlaps preamble weight loads)
    float4 buf[4];
    {
        const float* base = msa + ((size_t)(wid * 2 + lh) * LRES + blockIdx.x) * 64 + lq4 * 4;
        #pragma unroll
        for (int j = 0; j < 4; ++j)
            buf[j] = *reinterpret_cast<const float4*>(base + (size_t)j * lnstep);
    }

    // ---------------- preamble (once): weights to SMEM ----------------
    #pragma unroll
    for (int i = 0; i < 8; ++i) {
        int idx = tid + i * NT;
        s->wc[idx >> 6][idx & 63] = g_wg[idx];
    }
    {
        int d = tid >> 3, j = tid & 7;
        s->wc[d][64 + j] = g_wk[tid];
        s->wc[d][72 + j] = g_wv[tid];
    }
    #pragma unroll
    for (int i = 0; i < 2; ++i) {
        int idx = tid + i * NT;
        ((float4*)s->wo)[idx] = ((const float4*)g_wo)[idx];
    }
    if (tid < 64) {
        s->lnw[tid] = g_lnw[tid];
        s->lnb[tid] = g_lnb[tid];
        s->bgv[tid] = g_bg[tid];
        s->bov[tid] = g_bo[tid];
    }
    float wqr[8];
    {
        int dg = tid >> 6, c = tid & 63;
        #pragma unroll
        for (int i = 0; i < 8; ++i) wqr[i] = g_wq[(8 * dg + i) * 64 + c];
    }
    __syncthreads();

    #pragma unroll 1
    for (int col = 0; col < 2; ++col) {
        const int l = blockIdx.x + 512 * col;
        const float* lnbase = msa + ((size_t)(wid * 2 + lh) * LRES + l) * 64 + lq4 * 4;

        // ---------------- LayerNorm -> xg transposed+swizzled (prefetch depth 4) ----------------
        {
            if (col > 0) {
                #pragma unroll
                for (int j = 0; j < 4; ++j)
                    buf[j] = *reinterpret_cast<const float4*>(lnbase + (size_t)j * lnstep);
            }
            float xacc0 = 0.f, xacc1 = 0.f, xacc2 = 0.f, xacc3 = 0.f;
            #pragma unroll 4
            for (int it = 0; it < 16; ++it) {
                float4 cur = buf[it & 3];
                if (it + 4 < 16)
                    buf[it & 3] = *reinterpret_cast<const float4*>(lnbase + (size_t)(it + 4) * lnstep);
                float sm = (cur.x + cur.y) + (cur.z + cur.w);
                float sq = fmaf(cur.x, cur.x, fmaf(cur.y, cur.y,
                           fmaf(cur.z, cur.z, cur.w * cur.w)));
                #pragma unroll
                for (int off = 1; off < 16; off <<= 1) {
                    sm += __shfl_xor_sync(0xffffffffu, sm, off);
                    sq += __shfl_xor_sync(0xffffffffu, sq, off);
                }
                float mu   = sm * (1.f / 64.f);
                float var  = sq * (1.f / 64.f) - mu * mu;
                float rstd = rsqrtf(var + LN_EPS);
                float mrs  = -mu * rstd;
                int row = it * 32 + wid * 2 + lh;
                int rb = row >> 2, r0 = row & 3;
                int c0 = 4 * lq4;
                float v0 = fmaf(fmaf(cur.x, rstd, mrs), s->lnw[c0 + 0], s->lnb[c0 + 0]);
                float v1 = fmaf(fmaf(cur.y, rstd, mrs), s->lnw[c0 + 1], s->lnb[c0 + 1]);
                float v2 = fmaf(fmaf(cur.z, rstd, mrs), s->lnw[c0 + 2], s->lnb[c0 + 2]);
                float v3 = fmaf(fmaf(cur.w, rstd, mrs), s->lnw[c0 + 3], s->lnb[c0 + 3]);
                s->xg[(c0 + 0) * NSEQ + 4 * (rb ^ swz(c0 + 0)) + r0] = v0;
                s->xg[(c0 + 1) * NSEQ + 4 * (rb ^ swz(c0 + 1)) + r0] = v1;
                s->xg[(c0 + 2) * NSEQ + 4 * (rb ^ swz(c0 + 2)) + r0] = v2;
                s->xg[(c0 + 3) * NSEQ + 4 * (rb ^ swz(c0 + 3)) + r0] = v3;
                xacc0 += v0; xacc1 += v1; xacc2 += v2; xacc3 += v3;
            }
            xacc0 += __shfl_xor_sync(0xffffffffu, xacc0, 16);
            xacc1 += __shfl_xor_sync(0xffffffffu, xacc1, 16);
            xacc2 += __shfl_xor_sync(0xffffffffu, xacc2, 16);
            xacc3 += __shfl_xor_sync(0xffffffffu, xacc3, 16);
            if (lane < 16) {
                float* xp = s->xpart + wid * 64 + 4 * lq4;
                xp[0] = xacc0; xp[1] = xacc1; xp[2] = xacc2; xp[3] = xacc3;
            }
        }
        __syncthreads();

        // xsum (consumed after next barrier)
        if (tid < 64) {
            float t = 0.f;
            #pragma unroll
            for (int w = 0; w < 16; ++w) t += s->xpart[w * 64 + tid];
            s->xsum[tid] = t;
        }

        // ---------------- pass A: fused gate + kv GEMM (8 rows x 8 cols + kv pair) ----------------
        const int r2a = 2 * rg, r2b = 2 * rg + 1;
        ull ga[8][4];
        ull ka[8];
        #pragma unroll
        for (int r = 0; r < 8; ++r) {
            ka[r] = 0;
            #pragma unroll
            for (int p = 0; p < 4; ++p) ga[r][p] = 0;
        }
        #pragma unroll 1
        for (int a = 0; a < 8; ++a) {
            const float* xcol  = s->xg + a * 8 * NSEQ;
            const int ea = (r2a ^ a) << 2;
            const int eb = (r2b ^ a) << 2;
            const float* wg_p  = &s->wc[a * 8][8 * cg];
            const float* wkv_p = &s->wc[a * 8][64 + 2 * cg];
            #pragma unroll
            for (int b = 0; b < 8; ++b) {
                float4 xa = *reinterpret_cast<const float4*>(xcol + b * NSEQ + (ea ^ (b << 2)));
                float4 xb = *reinterpret_cast<const float4*>(xcol + b * NSEQ + (eb ^ (b << 2)));
                ulonglong2 w0 = *reinterpret_cast<const ulonglong2*>(wg_p + b * 80);
                ulonglong2 w1 = *reinterpret_cast<const ulonglong2*>(wg_p + b * 80 + 4);
                ull wk = *reinterpret_cast<const ull*>(wkv_p + b * 80);
                ull t;
                t = splat2(xa.x); ffma2(ga[0][0],t,w0.x); ffma2(ga[0][1],t,w0.y); ffma2(ga[0][2],t,w1.x); ffma2(ga[0][3],t,w1.y); ffma2(ka[0],t,wk);
                t = splat2(xa.y); ffma2(ga[1][0],t,w0.x); ffma2(ga[1][1],t,w0.y); ffma2(ga[1][2],t,w1.x); ffma2(ga[1][3],t,w1.y); ffma2(ka[1],t,wk);
                t = splat2(xa.z); ffma2(ga[2][0],t,w0.x); ffma2(ga[2][1],t,w0.y); ffma2(ga[2][2],t,w1.x); ffma2(ga[2][3],t,w1.y); ffma2(ka[2],t,wk);
                t = splat2(xa.w); ffma2(ga[3][0],t,w0.x); ffma2(ga[3][1],t,w0.y); ffma2(ga[3][2],t,w1.x); ffma2(ga[3][3],t,w1.y); ffma2(ka[3],t,wk);
                t = splat2(xb.x); ffma2(ga[4][0],t,w0.x); ffma2(ga[4][1],t,w0.y); ffma2(ga[4][2],t,w1.x); ffma2(ga[4][3],t,w1.y); ffma2(ka[4],t,wk);
                t = splat2(xb.y); ffma2(ga[5][0],t,w0.x); ffma2(ga[5][1],t,w0.y); ffma2(ga[5][2],t,w1.x); ffma2(ga[5][3],t,w1.y); ffma2(ka[5],t,wk);
                t = splat2(xb.z); ffma2(ga[6][0],t,w0.x); ffma2(ga[6][1],t,w0.y); ffma2(ga[6][2],t,w1.x); ffma2(ga[6][3],t,w1.y); ffma2(ka[6],t,wk);
                t = splat2(xb.w); ffma2(ga[7][0],t,w0.x); ffma2(ga[7][1],t,w0.y); ffma2(ga[7][2],t,w1.x); ffma2(ga[7][3],t,w1.y); ffma2(ka[7],t,wk);
            }
        }
        __syncthreads();   // all xg reads done; safe to overwrite with G

        // gate epilogue: G = sigmoid(P + bg) -> xg
        #pragma unroll
        for (int c = 0; c < 8; ++c) {
            int colc = 8 * cg + c;
            float bgc = s->bgv[colc];
            float g[8];
            #pragma unroll
            for (int r = 0; r < 8; ++r) {
                float lo, hi;
                unpack2(ga[r][c >> 1], lo, hi);
                float v = (c & 1) ? hi : lo;
                g[r] = sigmoid_t(v + bgc);
            }
            float* dst = &s->xg[colc * NSEQ];
            *reinterpret_cast<float4*>(dst + 4 * (r2a ^ swz(colc))) = make_float4(g[0], g[1], g[2], g[3]);
            *reinterpret_cast<float4*>(dst + 4 * (r2b ^ swz(colc))) = make_float4(g[4], g[5], g[6], g[7]);
        }
        // kv epilogue
        if (cg < 4) {
            #pragma unroll
            for (int r = 0; r < 8; ++r)
                *reinterpret_cast<ull*>(&s->kbuf[8 * rg + r][2 * cg]) = ka[r];
        } else {
            int c0 = 2 * cg - 8;
            float a8[8], b8[8];
            #pragma unroll
            for (int r = 0; r < 8; ++r) unpack2(ka[r], a8[r], b8[r]);
            *reinterpret_cast<float4*>(&s->vT[c0 * NSEQ + 8 * rg])           = make_float4(a8[0], a8[1], a8[2], a8[3]);
            *reinterpret_cast<float4*>(&s->vT[c0 * NSEQ + 8 * rg + 4])       = make_float4(a8[4], a8[5], a8[6], a8[7]);
            *reinterpret_cast<float4*>(&s->vT[(c0 + 1) * NSEQ + 8 * rg])     = make_float4(b8[0], b8[1], b8[2], b8[3]);
            *reinterpret_cast<float4*>(&s->vT[(c0 + 1) * NSEQ + 8 * rg + 4]) = make_float4(b8[4], b8[5], b8[6], b8[7]);
        }
        // qvec partials
        {
            int dg = tid >> 6, c = tid & 63;
            float p = 0.f;
            #pragma unroll
            for (int i = 0; i < 8; ++i) p = fmaf(s->xsum[8 * dg + i], wqr[i], p);
            s->xpart[dg * 64 + c] = p;
        }
        __syncthreads();

        if (tid < 64) {
            float q = 0.f;
            #pragma unroll
            for (int dg = 0; dg < 8; ++dg) q += s->xpart[dg * 64 + tid];
            s->qvec[tid] = q * (float)(0.35355339059327373 / 512.0); // (1/sqrt(8))/N
        }
        __syncthreads();

        // ---------------- scores[h][n] ----------------
        {
            float4 k0 = *reinterpret_cast<const float4*>(&s->kbuf[tid][0]);
            float4 k1 = *reinterpret_cast<const float4*>(&s->kbuf[tid][4]);
            #pragma unroll
            for (int h = 0; h < 8; ++h) {
                const float* qf = &s->qvec[h * 8];
                float sc = qf[0]*k0.x + qf[1]*k0.y + qf[2]*k0.z + qf[3]*k0.w
                         + qf[4]*k1.x + qf[5]*k1.y + qf[6]*k1.z + qf[7]*k1.w;
                s->scores[h * NSEQ + tid] = sc;
            }
        }
        __syncthreads();

        // ---------------- softmax partials: 2 warps per head ----------------
        {
            int h = wid >> 1, half = wid & 1;
            const float* sc = s->scores + h * NSEQ + half * 256;
            float sv[8], m = -1e30f;
            #pragma unroll
            for (int k = 0; k < 8; ++k) { sv[k] = sc[lane + 32 * k]; m = fmaxf(m, sv[k]); }
            #pragma unroll
            for (int off = 16; off > 0; off >>= 1)
                m = fmaxf(m, __shfl_xor_sync(0xffffffffu, m, off));
            float ssum = 0.f, acc[8];
            #pragma unroll
            for (int d = 0; d < 8; ++d) acc[d] = 0.f;
            #pragma unroll
            for (int k = 0; k < 8; ++k) {
                float e = __expf(sv[k] - m);
                ssum += e;
                int n = half * 256 + lane + 32 * k;
                #pragma unroll
                for (int d = 0; d < 8; ++d) acc[d] = fmaf(e, s->vT[d * NSEQ + n], acc[d]);
            }
            #pragma unroll
            for (int off = 16; off > 0; off >>= 1) {
                ssum += __shfl_xor_sync(0xffffffffu, ssum, off);
                #pragma unroll
                for (int d = 0; d < 8; ++d) acc[d] += __shfl_xor_sync(0xffffffffu, acc[d], off);
            }
            if (lane == 0) {
                s->mpart[wid] = m;
                s->spart[wid] = ssum;
                #pragma unroll
                for (int d = 0; d < 8; ++d) s->opart[wid][d] = acc[d];
            }
        }
        __syncthreads();

        // ovec combine (exact two-way softmax merge)
        if (tid < 64) {
            int h = tid >> 3, d = tid & 7;
            float m0 = s->mpart[2 * h], m1 = s->mpart[2 * h + 1];
            float m = fmaxf(m0, m1);
            float e0 = __expf(m0 - m), e1 = __expf(m1 - m);
            float ss = s->spart[2 * h] * e0 + s->spart[2 * h + 1] * e1;
            float ov = s->opart[2 * h][d] * e0 + s->opart[2 * h + 1][d] * e1;
            s->ovec[8 * h + d] = ov / ss;
        }
        __syncthreads();

        // fold ovec into Wo -> scores area (Wo stays pristine for next column)
        float* wf = s->scores;
        #pragma unroll
        for (int i = 0; i < 2; ++i) {
            int idx = tid + i * NT;
            float4 w4 = ((float4*)s->wo)[idx];
            float ov = s->ovec[idx >> 4];
            w4.x *= ov; w4.y *= ov; w4.z *= ov; w4.w *= ov;
            ((float4*)wf)[idx] = w4;
        }
        __syncthreads();

        // ---------------- pass B: out = G @ Wo' + bo ----------------
        {
            ull acc[8][4];
            #pragma unroll
            for (int i = 0; i < 8; ++i)
                #pragma unroll
                for (int p = 0; p < 4; ++p) acc[i][p] = 0;

            #pragma unroll 1
            for (int a = 0; a < 8; ++a) {
                const float* gcol = s->xg + a * 8 * NSEQ;
                const int ea = (r2a ^ a) << 2;
                const int eb = (r2b ^ a) << 2;
                const float* wo_p = wf + (a * 8) * 64 + 8 * cg;
                #pragma unroll
                for (int b = 0; b < 8; ++b) {
                    float4 xa = *reinterpret_cast<const float4*>(gcol + b * NSEQ + (ea ^ (b << 2)));
                    float4 xb = *reinterpret_cast<const float4*>(gcol + b * NSEQ + (eb ^ (b << 2)));
                    ulonglong2 wA = *reinterpret_cast<const ulonglong2*>(wo_p + b * 64);
                    ulonglong2 wB = *reinterpret_cast<const ulonglong2*>(wo_p + b * 64 + 4);
                    ull t;
                    t = splat2(xa.x); ffma2(acc[0][0],t,wA.x); ffma2(acc[0][1],t,wA.y); ffma2(acc[0][2],t,wB.x); ffma2(acc[0][3],t,wB.y);
                    t = splat2(xa.y); ffma2(acc[1][0],t,wA.x); ffma2(acc[1][1],t,wA.y); ffma2(acc[1][2],t,wB.x); ffma2(acc[1][3],t,wB.y);
                    t = splat2(xa.z); ffma2(acc[2][0],t,wA.x); ffma2(acc[2][1],t,wA.y); ffma2(acc[2][2],t,wB.x); ffma2(acc[2][3],t,wB.y);
                    t = splat2(xa.w); ffma2(acc[3][0],t,wA.x); ffma2(acc[3][1],t,wA.y); ffma2(acc[3][2],t,wB.x); ffma2(acc[3][3],t,wB.y);
                    t = splat2(xb.x); ffma2(acc[4][0],t,wA.x); ffma2(acc[4][1],t,wA.y); ffma2(acc[4][2],t,wB.x); ffma2(acc[4][3],t,wB.y);
                    t = splat2(xb.y); ffma2(acc[5][0],t,wA.x); ffma2(acc[5][1],t,wA.y); ffma2(acc[5][2],t,wB.x); ffma2(acc[5][3],t,wB.y);
                    t = splat2(xb.z); ffma2(acc[6][0],t,wA.x); ffma2(acc[6][1],t,wA.y); ffma2(acc[6][2],t,wB.x); ffma2(acc[6][3],t,wB.y);
                    t = splat2(xb.w); ffma2(acc[7][0],t,wA.x); ffma2(acc[7][1],t,wA.y); ffma2(acc[7][2],t,wB.x); ffma2(acc[7][3],t,wB.y);
                }
            }

            const ulonglong2 boA = *reinterpret_cast<const ulonglong2*>(&s->bov[8 * cg]);
            const ulonglong2 boB = *reinterpret_cast<const ulonglong2*>(&s->bov[8 * cg + 4]);
            #pragma unroll
            for (int i = 0; i < 8; ++i) {
                size_t row = (size_t)(8 * rg + i);
                float* op = out + (row * LRES + l) * 64 + 8 * cg;
                ulonglong2 v0, v1;
                v0.x = add2(acc[i][0], boA.x); v0.y = add2(acc[i][1], boA.y);
                v1.x = add2(acc[i][2], boB.x); v1.y = add2(acc[i][3], boB.y);
                *reinterpret_cast<ulonglong2*>(op)     = v0;
                *reinterpret_cast<ulonglong2*>(op + 4) = v1;
            }
        }
        __syncthreads();   // protect xg/kbuf/vT reuse by next column
    }
}

extern "C" void kernel_launch(void* const* d_in, const int* in_sizes, int n_in,
                              void* d_out, int out_size) {
    const float* msa = (const float*)d_in[0];
    const float* lnw = (const float*)d_in[1];
    const float* lnb = (const float*)d_in[2];
    const float* wq  = (const float*)d_in[3];
    const float* wk  = (const float*)d_in[4];
    const float* wv  = (const float*)d_in[5];
    const float* wg  = (const float*)d_in[6];
    const float* bg  = (const float*)d_in[7];
    const float* wo  = (const float*)d_in[8];
    const float* bo  = (const float*)d_in[9];
    float* out = (float*)d_out;

    const int smem_bytes = (int)sizeof(Smem);
    cudaFuncSetAttribute(msa_col_attn_v14,
                         cudaFuncAttributeMaxDynamicSharedMemorySize, smem_bytes);
    msa_col_attn_v14<<<512, NT, smem_bytes>>>(
        msa, lnw, lnb, wq, wk, wv, wg, bg, wo, bo, out);
}

// round 15
// speedup vs baseline: 1.5479x; 1.1894x over previous
#include <cuda_runtime.h>
#include <math.h>

typedef unsigned long long ull;
typedef unsigned int u32;

namespace {
constexpr int NSEQ = 512;
constexpr int LRES = 1024;
constexpr int NT   = 512;
constexpr float LN_EPS = 1e-5f;

struct __align__(16) Smem {
    float xb[512 * 64];        // 128 KB: X fragment-native; then G transposed+swizzled
    float wA[64 * 80];         // 20 KB: frag-native tf32 [Wg|Wk|Wv], blocks of 64 per (kstep,ntile)
    float wo[64 * 64];         // 16 KB (ovec-folded in place before pass B)
    float kbuf[NSEQ][8];       // 16 KB
    float vT[8 * NSEQ];        // 16 KB
    float scores[8 * NSEQ];    // 16 KB
    float lnw[64], lnb[64], bgv[64], bov[64], xsum[64], qvec[64], ovec[64];
    float xpart[16 * 64];      // 4 KB
    float mpart[16], spart[16], opart[16][8];
};  // ~223.6 KB

__device__ __forceinline__ int swz(int c) { return ((c >> 3) ^ c) & 7; }
__device__ __forceinline__ void ffma2(ull& d_, ull a, ull b) {
    asm("fma.rn.f32x2 %0, %1, %2, %0;" : "+l"(d_) : "l"(a), "l"(b));
}
__device__ __forceinline__ ull splat2(float x) {
    ull r; asm("mov.b64 %0, {%1, %1};" : "=l"(r) : "f"(x)); return r;
}
__device__ __forceinline__ ull add2(ull a, ull b) {
    ull r; asm("add.rn.f32x2 %0, %1, %2;" : "=l"(r) : "l"(a), "l"(b)); return r;
}
__device__ __forceinline__ void unpack2(ull u, float& lo, float& hi) {
    asm("mov.b64 {%0, %1}, %2;" : "=f"(lo), "=f"(hi) : "l"(u));
}
__device__ __forceinline__ float sigmoid_t(float v) {
    float t; asm("tanh.approx.f32 %0, %1;" : "=f"(t) : "f"(v * 0.5f));
    return fmaf(t, 0.5f, 0.5f);
}
__device__ __forceinline__ float rna(float x) {
    float r; asm("cvt.rna.tf32.f32 %0, %1;" : "=f"(r) : "f"(x)); return r;
}
__device__ __forceinline__ void mma_tf32(float* d, const float4& a, const float2& b) {
    asm volatile(
        "mma.sync.aligned.m16n8k8.row.col.f32.tf32.tf32.f32 "
        "{%0,%1,%2,%3}, {%4,%5,%6,%7}, {%8,%9}, {%0,%1,%2,%3};"
        : "+f"(d[0]), "+f"(d[1]), "+f"(d[2]), "+f"(d[3])
        : "r"(__float_as_uint(a.x)), "r"(__float_as_uint(a.y)),
          "r"(__float_as_uint(a.z)), "r"(__float_as_uint(a.w)),
          "r"(__float_as_uint(b.x)), "r"(__float_as_uint(b.y)));
}
// fragment-native position of W element (d=k index, col n in [0,80))
__device__ __forceinline__ int wpos(int d, int n) {
    int block = (d >> 3) * 10 + (n >> 3);
    int lane_t = (n & 7) * 4 + (d & 3);
    return block * 64 + lane_t * 2 + ((d & 7) >> 2);
}
} // namespace

__global__ void __launch_bounds__(NT, 1)
msa_col_attn_v15(const float* __restrict__ msa,
                 const float* __restrict__ g_lnw, const float* __restrict__ g_lnb,
                 const float* __restrict__ g_wq,  const float* __restrict__ g_wk,
                 const float* __restrict__ g_wv,  const float* __restrict__ g_wg,
                 const float* __restrict__ g_bg,  const float* __restrict__ g_wo,
                 const float* __restrict__ g_bo,  float* __restrict__ out)
{
    extern __shared__ float smf[];
    Smem* s = reinterpret_cast<Smem*>(smf);
    const int tid  = threadIdx.x;
    const int l    = blockIdx.x;
    const int lane = tid & 31;
    const int wid  = tid >> 5;
    const int rg = tid >> 3;   // pass-B rows 8rg..8rg+7
    const int cg = tid & 7;    // pass-B cols 8cg..8cg+7

    // ---------------- preamble: weights ----------------
    #pragma unroll
    for (int i = 0; i < 8; ++i) {
        int idx = tid + i * NT;
        s->wA[wpos(idx >> 6, idx & 63)] = rna(g_wg[idx]);
    }
    {
        int d = tid >> 3, j = tid & 7;
        s->wA[wpos(d, 64 + j)] = rna(g_wk[tid]);
        s->wA[wpos(d, 72 + j)] = rna(g_wv[tid]);
    }
    #pragma unroll
    for (int i = 0; i < 2; ++i) {
        int idx = tid + i * NT;
        ((float4*)s->wo)[idx] = ((const float4*)g_wo)[idx];
    }
    if (tid < 64) {
        s->lnw[tid] = g_lnw[tid];
        s->lnb[tid] = g_lnb[tid];
        s->bgv[tid] = g_bg[tid];
        s->bov[tid] = g_bo[tid];
    }
    float wqr[8];
    {
        int dg = tid >> 6, c = tid & 63;
        #pragma unroll
        for (int i = 0; i < 8; ++i) wqr[i] = g_wq[(8 * dg + i) * 64 + c];
    }
    __syncthreads();

    // ---------------- LayerNorm -> xb (A-fragment-native, tf32-rounded) ----------------
    // warp covers 2 rows/iter; 16 lanes span one 256B row; prefetch depth 4
    {
        const int lq4 = lane & 15;
        const int lh  = lane >> 4;
        const size_t step = (size_t)32 * LRES * 64;
        const float* base = msa + ((size_t)(wid * 2 + lh) * LRES + l) * 64 + lq4 * 4;
        float xacc0 = 0.f, xacc1 = 0.f, xacc2 = 0.f, xacc3 = 0.f;
        float4 buf[4];
        #pragma unroll
        for (int j = 0; j < 4; ++j)
            buf[j] = *reinterpret_cast<const float4*>(base + (size_t)j * step);
        #pragma unroll 4
        for (int it = 0; it < 16; ++it) {
            float4 cur = buf[it & 3];
            if (it + 4 < 16)
                buf[it & 3] = *reinterpret_cast<const float4*>(base + (size_t)(it + 4) * step);
            float sm = (cur.x + cur.y) + (cur.z + cur.w);
            float sq = fmaf(cur.x, cur.x, fmaf(cur.y, cur.y,
                       fmaf(cur.z, cur.z, cur.w * cur.w)));
            #pragma unroll
            for (int off = 1; off < 16; off <<= 1) {
                sm += __shfl_xor_sync(0xffffffffu, sm, off);
                sq += __shfl_xor_sync(0xffffffffu, sq, off);
            }
            float mu   = sm * (1.f / 64.f);
            float var  = sq * (1.f / 64.f) - mu * mu;
            float rstd = rsqrtf(var + LN_EPS);
            float mrs  = -mu * rstd;
            int row = it * 32 + wid * 2 + lh;
            int c0 = 4 * lq4;
            float v0 = fmaf(fmaf(cur.x, rstd, mrs), s->lnw[c0 + 0], s->lnb[c0 + 0]);
            float v1 = fmaf(fmaf(cur.y, rstd, mrs), s->lnw[c0 + 1], s->lnb[c0 + 1]);
            float v2 = fmaf(fmaf(cur.z, rstd, mrs), s->lnw[c0 + 2], s->lnb[c0 + 2]);
            float v3 = fmaf(fmaf(cur.w, rstd, mrs), s->lnw[c0 + 3], s->lnb[c0 + 3]);
            // A-frag-native scatter: block (row>>4)*8 + (c0>>3), lane (r2*4+c2), reg (hc*2+hr)
            {
                int r2 = (row & 15) & 7, hr = (row & 15) >> 3;
                int bb = ((row >> 4) * 8 + (c0 >> 3)) * 128 + r2 * 16 + ((c0 & 7) >> 2) * 2 + hr;
                s->xb[bb + 0]  = rna(v0);
                s->xb[bb + 4]  = rna(v1);
                s->xb[bb + 8]  = rna(v2);
                s->xb[bb + 12] = rna(v3);
            }
            xacc0 += v0; xacc1 += v1; xacc2 += v2; xacc3 += v3;
        }
        xacc0 += __shfl_xor_sync(0xffffffffu, xacc0, 16);
        xacc1 += __shfl_xor_sync(0xffffffffu, xacc1, 16);
        xacc2 += __shfl_xor_sync(0xffffffffu, xacc2, 16);
        xacc3 += __shfl_xor_sync(0xffffffffu, xacc3, 16);
        if (lane < 16) {
            float* xp = s->xpart + wid * 64 + 4 * lq4;
            xp[0] = xacc0; xp[1] = xacc1; xp[2] = xacc2; xp[3] = xacc3;
        }
    }
    __syncthreads();

    // xsum (consumed after the next barrier)
    if (tid < 64) {
        float t = 0.f;
        #pragma unroll
        for (int w = 0; w < 16; ++w) t += s->xpart[w * 64 + tid];
        s->xsum[tid] = t;
    }

    // ---------------- pass A: tensor-core GEMM P = X @ [Wg|Wk|Wv] ----------------
    // warp handles m-tiles {2wid, 2wid+1}; 10 n-tiles; 8 k-steps (m16n8k8 tf32)
    float dacc[2][10][4];
    #pragma unroll
    for (int mt = 0; mt < 2; ++mt)
        #pragma unroll
        for (int nt = 0; nt < 10; ++nt)
            #pragma unroll
            for (int q = 0; q < 4; ++q) dacc[mt][nt][q] = 0.f;

    #pragma unroll
    for (int mt = 0; mt < 2; ++mt) {
        const int mtile = 2 * wid + mt;
        #pragma unroll
        for (int ks = 0; ks < 8; ++ks) {
            float4 af = *reinterpret_cast<const float4*>(
                s->xb + (mtile * 8 + ks) * 128 + lane * 4);
            const float* wb = s->wA + (ks * 10) * 64 + lane * 2;
            #pragma unroll
            for (int nt = 0; nt < 10; ++nt) {
                float2 bf = *reinterpret_cast<const float2*>(wb + nt * 64);
                mma_tf32(dacc[mt][nt], af, bf);
            }
        }
    }
    __syncthreads();   // all xb reads done; safe to overwrite with G

    // ---------------- epilogues (D-fragment scatter) ----------------
    {
        const int rfrag = lane >> 2;        // 0..7
        const int cfrag = (lane & 3) * 2;   // 0,2,4,6
        #pragma unroll
        for (int mt = 0; mt < 2; ++mt) {
            const int mtile = 2 * wid + mt;
            const int rA = mtile * 16 + rfrag, rB = rA + 8;
            // gate n-tiles 0..7 -> G transposed+swizzled into xb
            #pragma unroll
            for (int nt = 0; nt < 8; ++nt) {
                int colA = nt * 8 + cfrag, colB = colA + 1;
                float bA = s->bgv[colA], bB = s->bgv[colB];
                float g0 = sigmoid_t(dacc[mt][nt][0] + bA);
                float g1 = sigmoid_t(dacc[mt][nt][1] + bB);
                float g2 = sigmoid_t(dacc[mt][nt][2] + bA);
                float g3 = sigmoid_t(dacc[mt][nt][3] + bB);
                s->xb[colA * NSEQ + 4 * ((rA >> 2) ^ swz(colA)) + (rA & 3)] = g0;
                s->xb[colB * NSEQ + 4 * ((rA >> 2) ^ swz(colB)) + (rA & 3)] = g1;
                s->xb[colA * NSEQ + 4 * ((rB >> 2) ^ swz(colA)) + (rB & 3)] = g2;
                s->xb[colB * NSEQ + 4 * ((rB >> 2) ^ swz(colB)) + (rB & 3)] = g3;
            }
            // k (n-tile 8) -> kbuf row-major
            {
                ull k0, k1;
                asm("mov.b64 %0, {%1, %2};" : "=l"(k0) : "f"(dacc[mt][8][0]), "f"(dacc[mt][8][1]));
                asm("mov.b64 %0, {%1, %2};" : "=l"(k1) : "f"(dacc[mt][8][2]), "f"(dacc[mt][8][3]));
                *reinterpret_cast<ull*>(&s->kbuf[rA][cfrag]) = k0;
                *reinterpret_cast<ull*>(&s->kbuf[rB][cfrag]) = k1;
            }
            // v (n-tile 9) -> vT transposed
            {
                s->vT[cfrag * NSEQ + rA]       = dacc[mt][9][0];
                s->vT[(cfrag + 1) * NSEQ + rA] = dacc[mt][9][1];
                s->vT[cfrag * NSEQ + rB]       = dacc[mt][9][2];
                s->vT[(cfrag + 1) * NSEQ + rB] = dacc[mt][9][3];
            }
        }
    }
    // qvec partials (xsum written before previous barrier)
    {
        int dg = tid >> 6, c = tid & 63;
        float p = 0.f;
        #pragma unroll
        for (int i = 0; i < 8; ++i) p = fmaf(s->xsum[8 * dg + i], wqr[i], p);
        s->xpart[dg * 64 + c] = p;
    }
    __syncthreads();

    if (tid < 64) {
        float q = 0.f;
        #pragma unroll
        for (int dg = 0; dg < 8; ++dg) q += s->xpart[dg * 64 + tid];
        s->qvec[tid] = q * (float)(0.35355339059327373 / 512.0); // (1/sqrt(8))/N
    }
    __syncthreads();

    // ---------------- scores[h][n] ----------------
    {
        float4 k0 = *reinterpret_cast<const float4*>(&s->kbuf[tid][0]);
        float4 k1 = *reinterpret_cast<const float4*>(&s->kbuf[tid][4]);
        #pragma unroll
        for (int h = 0; h < 8; ++h) {
            const float* qf = &s->qvec[h * 8];
            float sc = qf[0]*k0.x + qf[1]*k0.y + qf[2]*k0.z + qf[3]*k0.w
                     + qf[4]*k1.x + qf[5]*k1.y + qf[6]*k1.z + qf[7]*k1.w;
            s->scores[h * NSEQ + tid] = sc;
        }
    }
    __syncthreads();

    // ---------------- softmax partials: 2 warps per head ----------------
    {
        int h = wid >> 1, half = wid & 1;
        const float* sc = s->scores + h * NSEQ + half * 256;
        float sv[8], m = -1e30f;
        #pragma unroll
        for (int k = 0; k < 8; ++k) { sv[k] = sc[lane + 32 * k]; m = fmaxf(m, sv[k]); }
        #pragma unroll
        for (int off = 16; off > 0; off >>= 1)
            m = fmaxf(m, __shfl_xor_sync(0xffffffffu, m, off));
        float ssum = 0.f, acc[8];
        #pragma unroll
        for (int d = 0; d < 8; ++d) acc[d] = 0.f;
        #pragma unroll
        for (int k = 0; k < 8; ++k) {
            float e = __expf(sv[k] - m);
            ssum += e;
            int n = half * 256 + lane + 32 * k;
            #pragma unroll
            for (int d = 0; d < 8; ++d) acc[d] = fmaf(e, s->vT[d * NSEQ + n], acc[d]);
        }
        #pragma unroll
        for (int off = 16; off > 0; off >>= 1) {
            ssum += __shfl_xor_sync(0xffffffffu, ssum, off);
            #pragma unroll
            for (int d = 0; d < 8; ++d) acc[d] += __shfl_xor_sync(0xffffffffu, acc[d], off);
        }
        if (lane == 0) {
            s->mpart[wid] = m;
            s->spart[wid] = ssum;
            #pragma unroll
            for (int d = 0; d < 8; ++d) s->opart[wid][d] = acc[d];
        }
    }
    __syncthreads();

    // ovec combine (exact two-way softmax merge)
    if (tid < 64) {
        int h = tid >> 3, d = tid & 7;
        float m0 = s->mpart[2 * h], m1 = s->mpart[2 * h + 1];
        float m = fmaxf(m0, m1);
        float e0 = __expf(m0 - m), e1 = __expf(m1 - m);
        float ss = s->spart[2 * h] * e0 + s->spart[2 * h + 1] * e1;
        float ov = s->opart[2 * h][d] * e0 + s->opart[2 * h + 1][d] * e1;
        s->ovec[8 * h + d] = ov / ss;
    }
    __syncthreads();

    // fold ovec into Wo rows
    #pragma unroll
    for (int i = 0; i < 2; ++i) {
        int idx = tid + i * NT;
        float4 w4 = ((float4*)s->wo)[idx];
        float ov = s->ovec[idx >> 4];
        w4.x *= ov; w4.y *= ov; w4.z *= ov; w4.w *= ov;
        ((float4*)s->wo)[idx] = w4;
    }
    __syncthreads();

    // ---------------- pass B: out = G @ Wo' + bo (FFMA2, exact) ----------------
    {
        const int r2a = 2 * rg, r2b = 2 * rg + 1;
        ull acc[8][4];
        #pragma unroll
        for (int i = 0; i < 8; ++i)
            #pragma unroll
            for (int p = 0; p < 4; ++p) acc[i][p] = 0;

        #pragma unroll 1
        for (int a = 0; a < 8; ++a) {
            const float* gcol = s->xb + a * 8 * NSEQ;
            const int ea = (r2a ^ a) << 2;
            const int eb = (r2b ^ a) << 2;
            const float* wo_p = s->wo + (a * 8) * 64 + 8 * cg;
            #pragma unroll
            for (int b = 0; b < 8; ++b) {
                float4 xa = *reinterpret_cast<const float4*>(gcol + b * NSEQ + (ea ^ (b << 2)));
                float4 xb4 = *reinterpret_cast<const float4*>(gcol + b * NSEQ + (eb ^ (b << 2)));
                ulonglong2 wAv = *reinterpret_cast<const ulonglong2*>(wo_p + b * 64);
                ulonglong2 wBv = *reinterpret_cast<const ulonglong2*>(wo_p + b * 64 + 4);
                ull t;
                t = splat2(xa.x);  ffma2(acc[0][0],t,wAv.x); ffma2(acc[0][1],t,wAv.y); ffma2(acc[0][2],t,wBv.x); ffma2(acc[0][3],t,wBv.y);
                t = splat2(xa.y);  ffma2(acc[1][0],t,wAv.x); ffma2(acc[1][1],t,wAv.y); ffma2(acc[1][2],t,wBv.x); ffma2(acc[1][3],t,wBv.y);
                t = splat2(xa.z);  ffma2(acc[2][0],t,wAv.x); ffma2(acc[2][1],t,wAv.y); ffma2(acc[2][2],t,wBv.x); ffma2(acc[2][3],t,wBv.y);
                t = splat2(xa.w);  ffma2(acc[3][0],t,wAv.x); ffma2(acc[3][1],t,wAv.y); ffma2(acc[3][2],t,wBv.x); ffma2(acc[3][3],t,wBv.y);
                t = splat2(xb4.x); ffma2(acc[4][0],t,wAv.x); ffma2(acc[4][1],t,wAv.y); ffma2(acc[4][2],t,wBv.x); ffma2(acc[4][3],t,wBv.y);
                t = splat2(xb4.y); ffma2(acc[5][0],t,wAv.x); ffma2(acc[5][1],t,wAv.y); ffma2(acc[5][2],t,wBv.x); ffma2(acc[5][3],t,wBv.y);
                t = splat2(xb4.z); ffma2(acc[6][0],t,wAv.x); ffma2(acc[6][1],t,wAv.y); ffma2(acc[6][2],t,wBv.x); ffma2(acc[6][3],t,wBv.y);
                t = splat2(xb4.w); ffma2(acc[7][0],t,wAv.x); ffma2(acc[7][1],t,wAv.y); ffma2(acc[7][2],t,wBv.x); ffma2(acc[7][3],t,wBv.y);
            }
        }

        const ulonglong2 boA = *reinterpret_cast<const ulonglong2*>(&s->bov[8 * cg]);
        const ulonglong2 boB = *reinterpret_cast<const ulonglong2*>(&s->bov[8 * cg + 4]);
        #pragma unroll
        for (int i = 0; i < 8; ++i) {
            size_t row = (size_t)(8 * rg + i);
            float* op = out + (row * LRES + l) * 64 + 8 * cg;
            ulonglong2 v0, v1;
            v0.x = add2(acc[i][0], boA.x); v0.y = add2(acc[i][1], boA.y);
            v1.x = add2(acc[i][2], boB.x); v1.y = add2(acc[i][3], boB.y);
            *reinterpret_cast<ulonglong2*>(op)     = v0;
            *reinterpret_cast<ulonglong2*>(op + 4) = v1;
        }
    }
}

extern "C" void kernel_launch(void* const* d_in, const int* in_sizes, int n_in,
                              void* d_out, int out_size) {
    const float* msa = (const float*)d_in[0];
    const float* lnw = (const float*)d_in[1];
    const float* lnb = (const float*)d_in[2];
    const float* wq  = (const float*)d_in[3];
    const float* wk  = (const float*)d_in[4];
    const float* wv  = (const float*)d_in[5];
    const float* wg  = (const float*)d_in[6];
    const float* bg  = (const float*)d_in[7];
    const float* wo  = (const float*)d_in[8];
    const float* bo  = (const float*)d_in[9];
    float* out = (float*)d_out;

    const int smem_bytes = (int)sizeof(Smem);
    cudaFuncSetAttribute(msa_col_attn_v15,
                         cudaFuncAttributeMaxDynamicSharedMemorySize, smem_bytes);
    msa_col_attn_v15<<<LRES, NT, smem_bytes>>>(
        msa, lnw, lnb, wq, wk, wv, wg, bg, wo, bo, out);
}

// round 16
// speedup vs baseline: 1.9180x; 1.2391x over previous
#include <cuda_runtime.h>
#include <math.h>

typedef unsigned long long ull;

namespace {
constexpr int NSEQ = 512;
constexpr int LRES = 1024;
constexpr int NT   = 512;
constexpr float LN_EPS = 1e-5f;

struct __align__(16) Smem {
    float xb[512 * 64];        // 128 KB: X fragment-native; then G transposed+swizzled
    float wA[64 * 80];         // 20 KB: frag-native tf32 [Wg|Wk|Wv]
    float wo[64 * 64];         // 16 KB (ovec-folded in place before pass B)
    float kbuf[NSEQ][8];       // 16 KB
    float vT[8 * NSEQ];        // 16 KB
    float scores[8 * NSEQ];    // 16 KB
    float lnw[64], lnb[64], bgv[64], bov[64], xsum[64], qvec[64], ovec[64];
    float xpart[16 * 64];      // 4 KB
    float mpart[16], spart[16], opart[16][8];
};

__device__ __forceinline__ int swz(int c) { return ((c >> 3) ^ c) & 7; }
__device__ __forceinline__ void ffma2(ull& d_, ull a, ull b) {
    asm("fma.rn.f32x2 %0, %1, %2, %0;" : "+l"(d_) : "l"(a), "l"(b));
}
__device__ __forceinline__ ull splat2(float x) {
    ull r; asm("mov.b64 %0, {%1, %1};" : "=l"(r) : "f"(x)); return r;
}
__device__ __forceinline__ ull add2(ull a, ull b) {
    ull r; asm("add.rn.f32x2 %0, %1, %2;" : "=l"(r) : "l"(a), "l"(b)); return r;
}
__device__ __forceinline__ float sigmoid_t(float v) {
    float t; asm("tanh.approx.f32 %0, %1;" : "=f"(t) : "f"(v * 0.5f));
    return fmaf(t, 0.5f, 0.5f);
}
__device__ __forceinline__ float rna(float x) {
    float r; asm("cvt.rna.tf32.f32 %0, %1;" : "=f"(r) : "f"(x)); return r;
}
__device__ __forceinline__ void mma_tf32(float* d, const float4& a, const float2& b) {
    asm volatile(
        "mma.sync.aligned.m16n8k8.row.col.f32.tf32.tf32.f32 "
        "{%0,%1,%2,%3}, {%4,%5,%6,%7}, {%8,%9}, {%0,%1,%2,%3};"
        : "+f"(d[0]), "+f"(d[1]), "+f"(d[2]), "+f"(d[3])
        : "r"(__float_as_uint(a.x)), "r"(__float_as_uint(a.y)),
          "r"(__float_as_uint(a.z)), "r"(__float_as_uint(a.w)),
          "r"(__float_as_uint(b.x)), "r"(__float_as_uint(b.y)));
}
// fragment-native position of W element (d=k index, col n in [0,80))
__device__ __forceinline__ int wpos(int d, int n) {
    int block = (d >> 3) * 10 + (n >> 3);
    int lane_t = (n & 7) * 4 + (d & 3);
    return block * 64 + lane_t * 2 + ((d & 7) >> 2);
}
} // namespace

__global__ void __launch_bounds__(NT, 1)
msa_col_attn_v16(const float* __restrict__ msa,
                 const float* __restrict__ g_lnw, const float* __restrict__ g_lnb,
                 const float* __restrict__ g_wq,  const float* __restrict__ g_wk,
                 const float* __restrict__ g_wv,  const float* __restrict__ g_wg,
                 const float* __restrict__ g_bg,  const float* __restrict__ g_wo,
                 const float* __restrict__ g_bo,  float* __restrict__ out)
{
    extern __shared__ float smf[];
    Smem* s = reinterpret_cast<Smem*>(smf);
    const int tid  = threadIdx.x;
    const int l    = blockIdx.x;
    const int lane = tid & 31;
    const int wid  = tid >> 5;
    const int rg = tid >> 3;   // pass-B rows 8rg..8rg+7
    const int cg = tid & 7;    // pass-B cols 8cg..8cg+7

    // ---------------- preamble: weights ----------------
    #pragma unroll
    for (int i = 0; i < 8; ++i) {
        int idx = tid + i * NT;
        s->wA[wpos(idx >> 6, idx & 63)] = rna(g_wg[idx]);
    }
    {
        int d = tid >> 3, j = tid & 7;
        s->wA[wpos(d, 64 + j)] = rna(g_wk[tid]);
        s->wA[wpos(d, 72 + j)] = rna(g_wv[tid]);
    }
    #pragma unroll
    for (int i = 0; i < 2; ++i) {
        int idx = tid + i * NT;
        ((float4*)s->wo)[idx] = ((const float4*)g_wo)[idx];
    }
    if (tid < 64) {
        s->lnw[tid] = g_lnw[tid];
        s->lnb[tid] = g_lnb[tid];
        s->bgv[tid] = g_bg[tid];
        s->bov[tid] = g_bo[tid];
    }
    float wqr[8];
    {
        int dg = tid >> 6, c = tid & 63;
        #pragma unroll
        for (int i = 0; i < 8; ++i) wqr[i] = g_wq[(8 * dg + i) * 64 + c];
    }
    __syncthreads();

    // ---------------- LayerNorm -> xb (A-fragment-native, tf32-rounded) ----------------
    {
        const int lq4 = lane & 15;
        const int lh  = lane >> 4;
        const size_t step = (size_t)32 * LRES * 64;
        const float* base = msa + ((size_t)(wid * 2 + lh) * LRES + l) * 64 + lq4 * 4;
        float xacc0 = 0.f, xacc1 = 0.f, xacc2 = 0.f, xacc3 = 0.f;
        float4 buf[4];
        #pragma unroll
        for (int j = 0; j < 4; ++j)
            buf[j] = *reinterpret_cast<const float4*>(base + (size_t)j * step);
        #pragma unroll 4
        for (int it = 0; it < 16; ++it) {
            float4 cur = buf[it & 3];
            if (it + 4 < 16)
                buf[it & 3] = *reinterpret_cast<const float4*>(base + (size_t)(it + 4) * step);
            float sm = (cur.x + cur.y) + (cur.z + cur.w);
            float sq = fmaf(cur.x, cur.x, fmaf(cur.y, cur.y,
                       fmaf(cur.z, cur.z, cur.w * cur.w)));
            #pragma unroll
            for (int off = 1; off < 16; off <<= 1) {
                sm += __shfl_xor_sync(0xffffffffu, sm, off);
                sq += __shfl_xor_sync(0xffffffffu, sq, off);
            }
            float mu   = sm * (1.f / 64.f);
            float var  = sq * (1.f / 64.f) - mu * mu;
            float rstd = rsqrtf(var + LN_EPS);
            float mrs  = -mu * rstd;
            int row = it * 32 + wid * 2 + lh;
            int c0 = 4 * lq4;
            float v0 = fmaf(fmaf(cur.x, rstd, mrs), s->lnw[c0 + 0], s->lnb[c0 + 0]);
            float v1 = fmaf(fmaf(cur.y, rstd, mrs), s->lnw[c0 + 1], s->lnb[c0 + 1]);
            float v2 = fmaf(fmaf(cur.z, rstd, mrs), s->lnw[c0 + 2], s->lnb[c0 + 2]);
            float v3 = fmaf(fmaf(cur.w, rstd, mrs), s->lnw[c0 + 3], s->lnb[c0 + 3]);
            {
                int r2 = (row & 15) & 7, hr = (row & 15) >> 3;
                int bb = ((row >> 4) * 8 + (c0 >> 3)) * 128 + r2 * 16 + ((c0 & 7) >> 2) * 2 + hr;
                s->xb[bb + 0]  = rna(v0);
                s->xb[bb + 4]  = rna(v1);
                s->xb[bb + 8]  = rna(v2);
                s->xb[bb + 12] = rna(v3);
            }
            xacc0 += v0; xacc1 += v1; xacc2 += v2; xacc3 += v3;
        }
        xacc0 += __shfl_xor_sync(0xffffffffu, xacc0, 16);
        xacc1 += __shfl_xor_sync(0xffffffffu, xacc1, 16);
        xacc2 += __shfl_xor_sync(0xffffffffu, xacc2, 16);
        xacc3 += __shfl_xor_sync(0xffffffffu, xacc3, 16);
        if (lane < 16) {
            float* xp = s->xpart + wid * 64 + 4 * lq4;
            xp[0] = xacc0; xp[1] = xacc1; xp[2] = xacc2; xp[3] = xacc3;
        }
    }
    __syncthreads();

    // xsum (consumed after the next barrier)
    if (tid < 64) {
        float t = 0.f;
        #pragma unroll
        for (int w = 0; w < 16; ++w) t += s->xpart[w * 64 + tid];
        s->xsum[tid] = t;
    }

    const int rfrag = lane >> 2;        // 0..7
    const int cfrag = (lane & 3) * 2;   // 0,2,4,6

    // ---------------- pass A1: k/v MMA (n-tiles 8,9), retire immediately ----------------
    {
        float dkv[2][2][4];
        #pragma unroll
        for (int mt = 0; mt < 2; ++mt)
            #pragma unroll
            for (int nt = 0; nt < 2; ++nt)
                #pragma unroll
                for (int q = 0; q < 4; ++q) dkv[mt][nt][q] = 0.f;
        #pragma unroll
        for (int mt = 0; mt < 2; ++mt) {
            const int mtile = 2 * wid + mt;
            #pragma unroll
            for (int ks = 0; ks < 8; ++ks) {
                float4 af = *reinterpret_cast<const float4*>(
                    s->xb + (mtile * 8 + ks) * 128 + lane * 4);
                const float* wb = s->wA + (ks * 10 + 8) * 64 + lane * 2;
                float2 b0 = *reinterpret_cast<const float2*>(wb);
                float2 b1 = *reinterpret_cast<const float2*>(wb + 64);
                mma_tf32(dkv[mt][0], af, b0);
                mma_tf32(dkv[mt][1], af, b1);
            }
        }
        // immediate epilogue (kbuf/vT disjoint from xb; consumed after later barriers)
        #pragma unroll
        for (int mt = 0; mt < 2; ++mt) {
            const int mtile = 2 * wid + mt;
            const int rA = mtile * 16 + rfrag, rB = rA + 8;
            ull k0, k1;
            asm("mov.b64 %0, {%1, %2};" : "=l"(k0) : "f"(dkv[mt][0][0]), "f"(dkv[mt][0][1]));
            asm("mov.b64 %0, {%1, %2};" : "=l"(k1) : "f"(dkv[mt][0][2]), "f"(dkv[mt][0][3]));
            *reinterpret_cast<ull*>(&s->kbuf[rA][cfrag]) = k0;
            *reinterpret_cast<ull*>(&s->kbuf[rB][cfrag]) = k1;
            s->vT[cfrag * NSEQ + rA]       = dkv[mt][1][0];
            s->vT[(cfrag + 1) * NSEQ + rA] = dkv[mt][1][1];
            s->vT[cfrag * NSEQ + rB]       = dkv[mt][1][2];
            s->vT[(cfrag + 1) * NSEQ + rB] = dkv[mt][1][3];
        }
    }

    // ---------------- pass A2: gate MMA (n-tiles 0..7) ----------------
    float dacc[2][8][4];
    #pragma unroll
    for (int mt = 0; mt < 2; ++mt)
        #pragma unroll
        for (int nt = 0; nt < 8; ++nt)
            #pragma unroll
            for (int q = 0; q < 4; ++q) dacc[mt][nt][q] = 0.f;

    #pragma unroll
    for (int mt = 0; mt < 2; ++mt) {
        const int mtile = 2 * wid + mt;
        #pragma unroll
        for (int ks = 0; ks < 8; ++ks) {
            float4 af = *reinterpret_cast<const float4*>(
                s->xb + (mtile * 8 + ks) * 128 + lane * 4);
            const float* wb = s->wA + (ks * 10) * 64 + lane * 2;
            #pragma unroll
            for (int nt = 0; nt < 8; ++nt) {
                float2 bf = *reinterpret_cast<const float2*>(wb + nt * 64);
                mma_tf32(dacc[mt][nt], af, bf);
            }
        }
    }
    __syncthreads();   // all xb reads done; safe to overwrite with G

    // ---------------- gate epilogue (D-fragment scatter) ----------------
    #pragma unroll
    for (int mt = 0; mt < 2; ++mt) {
        const int mtile = 2 * wid + mt;
        const int rA = mtile * 16 + rfrag, rB = rA + 8;
        #pragma unroll
        for (int nt = 0; nt < 8; ++nt) {
            int colA = nt * 8 + cfrag, colB = colA + 1;
            float bA = s->bgv[colA], bB = s->bgv[colB];
            float g0 = sigmoid_t(dacc[mt][nt][0] + bA);
            float g1 = sigmoid_t(dacc[mt][nt][1] + bB);
            float g2 = sigmoid_t(dacc[mt][nt][2] + bA);
            float g3 = sigmoid_t(dacc[mt][nt][3] + bB);
            s->xb[colA * NSEQ + 4 * ((rA >> 2) ^ swz(colA)) + (rA & 3)] = g0;
            s->xb[colB * NSEQ + 4 * ((rA >> 2) ^ swz(colB)) + (rA & 3)] = g1;
            s->xb[colA * NSEQ + 4 * ((rB >> 2) ^ swz(colA)) + (rB & 3)] = g2;
            s->xb[colB * NSEQ + 4 * ((rB >> 2) ^ swz(colB)) + (rB & 3)] = g3;
        }
    }
    // qvec partials (xsum written before previous barrier)
    {
        int dg = tid >> 6, c = tid & 63;
        float p = 0.f;
        #pragma unroll
        for (int i = 0; i < 8; ++i) p = fmaf(s->xsum[8 * dg + i], wqr[i], p);
        s->xpart[dg * 64 + c] = p;
    }
    __syncthreads();

    if (tid < 64) {
        float q = 0.f;
        #pragma unroll
        for (int dg = 0; dg < 8; ++dg) q += s->xpart[dg * 64 + tid];
        s->qvec[tid] = q * (float)(0.35355339059327373 / 512.0); // (1/sqrt(8))/N
    }
    __syncthreads();

    // ---------------- scores[h][n] ----------------
    {
        float4 k0 = *reinterpret_cast<const float4*>(&s->kbuf[tid][0]);
        float4 k1 = *reinterpret_cast<const float4*>(&s->kbuf[tid][4]);
        #pragma unroll
        for (int h = 0; h < 8; ++h) {
            const float* qf = &s->qvec[h * 8];
            float sc = qf[0]*k0.x + qf[1]*k0.y + qf[2]*k0.z + qf[3]*k0.w
                     + qf[4]*k1.x + qf[5]*k1.y + qf[6]*k1.z + qf[7]*k1.w;
            s->scores[h * NSEQ + tid] = sc;
        }
    }
    __syncthreads();

    // ---------------- softmax partials: 2 warps per head ----------------
    {
        int h = wid >> 1, half = wid & 1;
        const float* sc = s->scores + h * NSEQ + half * 256;
        float sv[8], m = -1e30f;
        #pragma unroll
        for (int k = 0; k < 8; ++k) { sv[k] = sc[lane + 32 * k]; m = fmaxf(m, sv[k]); }
        #pragma unroll
        for (int off = 16; off > 0; off >>= 1)
            m = fmaxf(m, __shfl_xor_sync(0xffffffffu, m, off));
        float ssum = 0.f, acc[8];
        #pragma unroll
        for (int d = 0; d < 8; ++d) acc[d] = 0.f;
        #pragma unroll
        for (int k = 0; k < 8; ++k) {
            float e = __expf(sv[k] - m);
            ssum += e;
            int n = half * 256 + lane + 32 * k;
            #pragma unroll
            for (int d = 0; d < 8; ++d) acc[d] = fmaf(e, s->vT[d * NSEQ + n], acc[d]);
        }
        #pragma unroll
        for (int off = 16; off > 0; off >>= 1) {
            ssum += __shfl_xor_sync(0xffffffffu, ssum, off);
            #pragma unroll
            for (int d = 0; d < 8; ++d) acc[d] += __shfl_xor_sync(0xffffffffu, acc[d], off);
        }
        if (lane == 0) {
            s->mpart[wid] = m;
            s->spart[wid] = ssum;
            #pragma unroll
            for (int d = 0; d < 8; ++d) s->opart[wid][d] = acc[d];
        }
    }
    __syncthreads();

    // ovec combine (exact two-way softmax merge)
    if (tid < 64) {
        int h = tid >> 3, d = tid & 7;
        float m0 = s->mpart[2 * h], m1 = s->mpart[2 * h + 1];
        float m = fmaxf(m0, m1);
        float e0 = __expf(m0 - m), e1 = __expf(m1 - m);
        float ss = s->spart[2 * h] * e0 + s->spart[2 * h + 1] * e1;
        float ov = s->opart[2 * h][d] * e0 + s->opart[2 * h + 1][d] * e1;
        s->ovec[8 * h + d] = ov / ss;
    }
    __syncthreads();

    // fold ovec into Wo rows
    #pragma unroll
    for (int i = 0; i < 2; ++i) {
        int idx = tid + i * NT;
        float4 w4 = ((float4*)s->wo)[idx];
        float ov = s->ovec[idx >> 4];
        w4.x *= ov; w4.y *= ov; w4.z *= ov; w4.w *= ov;
        ((float4*)s->wo)[idx] = w4;
    }
    __syncthreads();

    // ---------------- pass B: out = G @ Wo' + bo (FFMA2, exact) ----------------
    {
        const int r2a = 2 * rg, r2b = 2 * rg + 1;
        ull acc[8][4];
        #pragma unroll
        for (int i = 0; i < 8; ++i)
            #pragma unroll
            for (int p = 0; p < 4; ++p) acc[i][p] = 0;

        #pragma unroll 1
        for (int a = 0; a < 8; ++a) {
            const float* gcol = s->xb + a * 8 * NSEQ;
            const int ea = (r2a ^ a) << 2;
            const int eb = (r2b ^ a) << 2;
            const float* wo_p = s->wo + (a * 8) * 64 + 8 * cg;
            #pragma unroll
            for (int b = 0; b < 8; ++b) {
                float4 xa = *reinterpret_cast<const float4*>(gcol + b * NSEQ + (ea ^ (b << 2)));
                float4 xb4 = *reinterpret_cast<const float4*>(gcol + b * NSEQ + (eb ^ (b << 2)));
                ulonglong2 wAv = *reinterpret_cast<const ulonglong2*>(wo_p + b * 64);
                ulonglong2 wBv = *reinterpret_cast<const ulonglong2*>(wo_p + b * 64 + 4);
                ull t;
                t = splat2(xa.x);  ffma2(acc[0][0],t,wAv.x); ffma2(acc[0][1],t,wAv.y); ffma2(acc[0][2],t,wBv.x); ffma2(acc[0][3],t,wBv.y);
                t = splat2(xa.y);  ffma2(acc[1][0],t,wAv.x); ffma2(acc[1][1],t,wAv.y); ffma2(acc[1][2],t,wBv.x); ffma2(acc[1][3],t,wBv.y);
                t = splat2(xa.z);  ffma2(acc[2][0],t,wAv.x); ffma2(acc[2][1],t,wAv.y); ffma2(acc[2][2],t,wBv.x); ffma2(acc[2][3],t,wBv.y);
                t = splat2(xa.w);  ffma2(acc[3][0],t,wAv.x); ffma2(acc[3][1],t,wAv.y); ffma2(acc[3][2],t,wBv.x); ffma2(acc[3][3],t,wBv.y);
                t = splat2(xb4.x); ffma2(acc[4][0],t,wAv.x); ffma2(acc[4][1],t,wAv.y); ffma2(acc[4][2],t,wBv.x); ffma2(acc[4][3],t,wBv.y);
                t = splat2(xb4.y); ffma2(acc[5][0],t,wAv.x); ffma2(acc[5][1],t,wAv.y); ffma2(acc[5][2],t,wBv.x); ffma2(acc[5][3],t,wBv.y);
                t = splat2(xb4.z); ffma2(acc[6][0],t,wAv.x); ffma2(acc[6][1],t,wAv.y); ffma2(acc[6][2],t,wBv.x); ffma2(acc[6][3],t,wBv.y);
                t = splat2(xb4.w); ffma2(acc[7][0],t,wAv.x); ffma2(acc[7][1],t,wAv.y); ffma2(acc[7][2],t,wBv.x); ffma2(acc[7][3],t,wBv.y);
            }
        }

        const ulonglong2 boA = *reinterpret_cast<const ulonglong2*>(&s->bov[8 * cg]);
        const ulonglong2 boB = *reinterpret_cast<const ulonglong2*>(&s->bov[8 * cg + 4]);
        #pragma unroll
        for (int i = 0; i < 8; ++i) {
            size_t row = (size_t)(8 * rg + i);
            float* op = out + (row * LRES + l) * 64 + 8 * cg;
            ulonglong2 v0, v1;
            v0.x = add2(acc[i][0], boA.x); v0.y = add2(acc[i][1], boA.y);
            v1.x = add2(acc[i][2], boB.x); v1.y = add2(acc[i][3], boB.y);
            *reinterpret_cast<ulonglong2*>(op)     = v0;
            *reinterpret_cast<ulonglong2*>(op + 4) = v1;
        }
    }
}

extern "C" void kernel_launch(void* const* d_in, const int* in_sizes, int n_in,
                              void* d_out, int out_size) {
    const float* msa = (const float*)d_in[0];
    const float* lnw = (const float*)d_in[1];
    const float* lnb = (const float*)d_in[2];
    const float* wq  = (const float*)d_in[3];
    const float* wk  = (const float*)d_in[4];
    const float* wv  = (const float*)d_in[5];
    const float* wg  = (const float*)d_in[6];
    const float* bg  = (const float*)d_in[7];
    const float* wo  = (const float*)d_in[8];
    const float* bo  = (const float*)d_in[9];
    float* out = (float*)d_out;

    const int smem_bytes = (int)sizeof(Smem);
    cudaFuncSetAttribute(msa_col_attn_v16,
                         cudaFuncAttributeMaxDynamicSharedMemorySize, smem_bytes);
    msa_col_attn_v16<<<LRES, NT, smem_bytes>>>(
        msa, lnw, lnb, wq, wk, wv, wg, bg, wo, bo, out);
}

// round 17
// speedup vs baseline: 2.6082x; 1.3598x over previous
#include <cuda_runtime.h>
#include <math.h>

typedef unsigned long long ull;

namespace {
constexpr int NSEQ = 512;
constexpr int LRES = 1024;
constexpr int NT   = 512;
constexpr float LN_EPS = 1e-5f;

struct __align__(16) Smem {
    float xb[512 * 64];        // 128 KB: X A-frag-native; then G A-frag-native
    float wA[64 * 80];         // 20 KB: B-frag-native tf32 [Wg|Wk|Wv]
    float wo[64 * 64];         // 16 KB row-major (pristine)
    float kbuf[NSEQ][8];       // 16 KB
    float vT[8 * NSEQ];        // 16 KB
    float scores[8 * NSEQ];    // 16 KB: scores; later B-frag-native ovec*Wo (4096 floats)
    float lnw[64], lnb[64], bgv[64], bov[64], xsum[64], qvec[64], ovec[64];
    float xpart[16 * 64];      // 4 KB
    float mpart[16], spart[16], opart[16][8];
};

__device__ __forceinline__ float sigmoid_t(float v) {
    float t; asm("tanh.approx.f32 %0, %1;" : "=f"(t) : "f"(v * 0.5f));
    return fmaf(t, 0.5f, 0.5f);
}
__device__ __forceinline__ float rna(float x) {
    float r; asm("cvt.rna.tf32.f32 %0, %1;" : "=f"(r) : "f"(x)); return r;
}
__device__ __forceinline__ void mma_tf32(float* d, const float4& a, const float2& b) {
    asm volatile(
        "mma.sync.aligned.m16n8k8.row.col.f32.tf32.tf32.f32 "
        "{%0,%1,%2,%3}, {%4,%5,%6,%7}, {%8,%9}, {%0,%1,%2,%3};"
        : "+f"(d[0]), "+f"(d[1]), "+f"(d[2]), "+f"(d[3])
        : "r"(__float_as_uint(a.x)), "r"(__float_as_uint(a.y)),
          "r"(__float_as_uint(a.z)), "r"(__float_as_uint(a.w)),
          "r"(__float_as_uint(b.x)), "r"(__float_as_uint(b.y)));
}
// B-frag-native position, 10 n-tiles wide (pass A weights)
__device__ __forceinline__ int wpos(int d, int n) {
    int block = (d >> 3) * 10 + (n >> 3);
    int lane_t = (n & 7) * 4 + (d & 3);
    return block * 64 + lane_t * 2 + ((d & 7) >> 2);
}
// B-frag-native position, 8 n-tiles wide (pass B weights)
__device__ __forceinline__ int wpos8(int d, int n) {
    int block = (d >> 3) * 8 + (n >> 3);
    int lane_t = (n & 7) * 4 + (d & 3);
    return block * 64 + lane_t * 2 + ((d & 7) >> 2);
}
} // namespace

__global__ void __launch_bounds__(NT, 1)
msa_col_attn_v17(const float* __restrict__ msa,
                 const float* __restrict__ g_lnw, const float* __restrict__ g_lnb,
                 const float* __restrict__ g_wq,  const float* __restrict__ g_wk,
                 const float* __restrict__ g_wv,  const float* __restrict__ g_wg,
                 const float* __restrict__ g_bg,  const float* __restrict__ g_wo,
                 const float* __restrict__ g_bo,  float* __restrict__ out)
{
    extern __shared__ float smf[];
    Smem* s = reinterpret_cast<Smem*>(smf);
    const int tid  = threadIdx.x;
    const int l    = blockIdx.x;
    const int lane = tid & 31;
    const int wid  = tid >> 5;

    // ---------------- preamble: weights ----------------
    #pragma unroll
    for (int i = 0; i < 8; ++i) {
        int idx = tid + i * NT;
        s->wA[wpos(idx >> 6, idx & 63)] = rna(g_wg[idx]);
    }
    {
        int d = tid >> 3, j = tid & 7;
        s->wA[wpos(d, 64 + j)] = rna(g_wk[tid]);
        s->wA[wpos(d, 72 + j)] = rna(g_wv[tid]);
    }
    #pragma unroll
    for (int i = 0; i < 2; ++i) {
        int idx = tid + i * NT;
        ((float4*)s->wo)[idx] = ((const float4*)g_wo)[idx];
    }
    if (tid < 64) {
        s->lnw[tid] = g_lnw[tid];
        s->lnb[tid] = g_lnb[tid];
        s->bgv[tid] = g_bg[tid];
        s->bov[tid] = g_bo[tid];
    }
    float wqr[8];
    {
        int dg = tid >> 6, c = tid & 63;
        #pragma unroll
        for (int i = 0; i < 8; ++i) wqr[i] = g_wq[(8 * dg + i) * 64 + c];
    }
    __syncthreads();

    // ---------------- LayerNorm -> xb (A-frag-native, tf32-rounded) ----------------
    {
        const int lq4 = lane & 15;
        const int lh  = lane >> 4;
        const size_t step = (size_t)32 * LRES * 64;
        const float* base = msa + ((size_t)(wid * 2 + lh) * LRES + l) * 64 + lq4 * 4;
        float xacc0 = 0.f, xacc1 = 0.f, xacc2 = 0.f, xacc3 = 0.f;
        float4 buf[4];
        #pragma unroll
        for (int j = 0; j < 4; ++j)
            buf[j] = *reinterpret_cast<const float4*>(base + (size_t)j * step);
        #pragma unroll 4
        for (int it = 0; it < 16; ++it) {
            float4 cur = buf[it & 3];
            if (it + 4 < 16)
                buf[it & 3] = *reinterpret_cast<const float4*>(base + (size_t)(it + 4) * step);
            float sm = (cur.x + cur.y) + (cur.z + cur.w);
            float sq = fmaf(cur.x, cur.x, fmaf(cur.y, cur.y,
                       fmaf(cur.z, cur.z, cur.w * cur.w)));
            #pragma unroll
            for (int off = 1; off < 16; off <<= 1) {
                sm += __shfl_xor_sync(0xffffffffu, sm, off);
                sq += __shfl_xor_sync(0xffffffffu, sq, off);
            }
            float mu   = sm * (1.f / 64.f);
            float var  = sq * (1.f / 64.f) - mu * mu;
            float rstd = rsqrtf(var + LN_EPS);
            float mrs  = -mu * rstd;
            int row = it * 32 + wid * 2 + lh;
            int c0 = 4 * lq4;
            float v0 = fmaf(fmaf(cur.x, rstd, mrs), s->lnw[c0 + 0], s->lnb[c0 + 0]);
            float v1 = fmaf(fmaf(cur.y, rstd, mrs), s->lnw[c0 + 1], s->lnb[c0 + 1]);
            float v2 = fmaf(fmaf(cur.z, rstd, mrs), s->lnw[c0 + 2], s->lnb[c0 + 2]);
            float v3 = fmaf(fmaf(cur.w, rstd, mrs), s->lnw[c0 + 3], s->lnb[c0 + 3]);
            {
                int r2 = row & 7, hr = (row & 15) >> 3;
                int bb = ((row >> 4) * 8 + (c0 >> 3)) * 128 + r2 * 16 + ((c0 & 7) >> 2) * 2 + hr;
                s->xb[bb + 0]  = rna(v0);
                s->xb[bb + 4]  = rna(v1);
                s->xb[bb + 8]  = rna(v2);
                s->xb[bb + 12] = rna(v3);
            }
            xacc0 += v0; xacc1 += v1; xacc2 += v2; xacc3 += v3;
        }
        xacc0 += __shfl_xor_sync(0xffffffffu, xacc0, 16);
        xacc1 += __shfl_xor_sync(0xffffffffu, xacc1, 16);
        xacc2 += __shfl_xor_sync(0xffffffffu, xacc2, 16);
        xacc3 += __shfl_xor_sync(0xffffffffu, xacc3, 16);
        if (lane < 16) {
            float* xp = s->xpart + wid * 64 + 4 * lq4;
            xp[0] = xacc0; xp[1] = xacc1; xp[2] = xacc2; xp[3] = xacc3;
        }
    }
    __syncthreads();

    // xsum (consumed after the next barrier)
    if (tid < 64) {
        float t = 0.f;
        #pragma unroll
        for (int w = 0; w < 16; ++w) t += s->xpart[w * 64 + tid];
        s->xsum[tid] = t;
    }

    const int rfrag = lane >> 2;        // 0..7
    const int cfrag = (lane & 3) * 2;   // 0,2,4,6

    // ---------------- pass A1: k/v MMA (n-tiles 8,9), retire immediately ----------------
    {
        float dkv[2][2][4];
        #pragma unroll
        for (int mt = 0; mt < 2; ++mt)
            #pragma unroll
            for (int nt = 0; nt < 2; ++nt)
                #pragma unroll
                for (int q = 0; q < 4; ++q) dkv[mt][nt][q] = 0.f;
        #pragma unroll
        for (int mt = 0; mt < 2; ++mt) {
            const int mtile = 2 * wid + mt;
            #pragma unroll
            for (int ks = 0; ks < 8; ++ks) {
                float4 af = *reinterpret_cast<const float4*>(
                    s->xb + (mtile * 8 + ks) * 128 + lane * 4);
                const float* wb = s->wA + (ks * 10 + 8) * 64 + lane * 2;
                float2 b0 = *reinterpret_cast<const float2*>(wb);
                float2 b1 = *reinterpret_cast<const float2*>(wb + 64);
                mma_tf32(dkv[mt][0], af, b0);
                mma_tf32(dkv[mt][1], af, b1);
            }
        }
        #pragma unroll
        for (int mt = 0; mt < 2; ++mt) {
            const int mtile = 2 * wid + mt;
            const int rA = mtile * 16 + rfrag, rB = rA + 8;
            ull k0, k1;
            asm("mov.b64 %0, {%1, %2};" : "=l"(k0) : "f"(dkv[mt][0][0]), "f"(dkv[mt][0][1]));
            asm("mov.b64 %0, {%1, %2};" : "=l"(k1) : "f"(dkv[mt][0][2]), "f"(dkv[mt][0][3]));
            *reinterpret_cast<ull*>(&s->kbuf[rA][cfrag]) = k0;
            *reinterpret_cast<ull*>(&s->kbuf[rB][cfrag]) = k1;
            s->vT[cfrag * NSEQ + rA]       = dkv[mt][1][0];
            s->vT[(cfrag + 1) * NSEQ + rA] = dkv[mt][1][1];
            s->vT[cfrag * NSEQ + rB]       = dkv[mt][1][2];
            s->vT[(cfrag + 1) * NSEQ + rB] = dkv[mt][1][3];
        }
    }

    // ---------------- pass A2: gate MMA (n-tiles 0..7) ----------------
    float dacc[2][8][4];
    #pragma unroll
    for (int mt = 0; mt < 2; ++mt)
        #pragma unroll
        for (int nt = 0; nt < 8; ++nt)
            #pragma unroll
            for (int q = 0; q < 4; ++q) dacc[mt][nt][q] = 0.f;

    #pragma unroll
    for (int mt = 0; mt < 2; ++mt) {
        const int mtile = 2 * wid + mt;
        #pragma unroll
        for (int ks = 0; ks < 8; ++ks) {
            float4 af = *reinterpret_cast<const float4*>(
                s->xb + (mtile * 8 + ks) * 128 + lane * 4);
            const float* wb = s->wA + (ks * 10) * 64 + lane * 2;
            #pragma unroll
            for (int nt = 0; nt < 8; ++nt) {
                float2 bf = *reinterpret_cast<const float2*>(wb + nt * 64);
                mma_tf32(dacc[mt][nt], af, bf);
            }
        }
    }
    __syncthreads();   // all xb reads done; safe to overwrite with G

    // ---------------- gate epilogue: G -> xb in A-frag-native layout (tf32) ----------------
    // For pass B GEMM: G row = sequence n (m-dim), G col = gate feature (k-dim)
    #pragma unroll
    for (int mt = 0; mt < 2; ++mt) {
        const int mtile = 2 * wid + mt;
        #pragma unroll
        for (int nt = 0; nt < 8; ++nt) {
            int colA = nt * 8 + cfrag, colB = colA + 1;
            float bA = s->bgv[colA], bB = s->bgv[colB];
            float g0 = sigmoid_t(dacc[mt][nt][0] + bA);   // (rA, colA)
            float g1 = sigmoid_t(dacc[mt][nt][1] + bB);   // (rA, colB)
            float g2 = sigmoid_t(dacc[mt][nt][2] + bA);   // (rB, colA)
            float g3 = sigmoid_t(dacc[mt][nt][3] + bB);   // (rB, colB)
            int boff = (mtile * 8 + nt) * 128 + rfrag * 16 + (cfrag & 3) * 4 + (cfrag >> 2) * 2;
            s->xb[boff + 0] = rna(g0);
            s->xb[boff + 4] = rna(g1);
            s->xb[boff + 1] = rna(g2);
            s->xb[boff + 5] = rna(g3);
        }
    }
    // qvec partials (xsum written before previous barrier)
    {
        int dg = tid >> 6, c = tid & 63;
        float p = 0.f;
        #pragma unroll
        for (int i = 0; i < 8; ++i) p = fmaf(s->xsum[8 * dg + i], wqr[i], p);
        s->xpart[dg * 64 + c] = p;
    }
    __syncthreads();

    if (tid < 64) {
        float q = 0.f;
        #pragma unroll
        for (int dg = 0; dg < 8; ++dg) q += s->xpart[dg * 64 + tid];
        s->qvec[tid] = q * (float)(0.35355339059327373 / 512.0); // (1/sqrt(8))/N
    }
    __syncthreads();

    // ---------------- scores[h][n] ----------------
    {
        float4 k0 = *reinterpret_cast<const float4*>(&s->kbuf[tid][0]);
        float4 k1 = *reinterpret_cast<const float4*>(&s->kbuf[tid][4]);
        #pragma unroll
        for (int h = 0; h < 8; ++h) {
            const float* qf = &s->qvec[h * 8];
            float sc = qf[0]*k0.x + qf[1]*k0.y + qf[2]*k0.z + qf[3]*k0.w
                     + qf[4]*k1.x + qf[5]*k1.y + qf[6]*k1.z + qf[7]*k1.w;
            s->scores[h * NSEQ + tid] = sc;
        }
    }
    __syncthreads();

    // ---------------- softmax partials: 2 warps per head ----------------
    {
        int h = wid >> 1, half = wid & 1;
        const float* sc = s->scores + h * NSEQ + half * 256;
        float sv[8], m = -1e30f;
        #pragma unroll
        for (int k = 0; k < 8; ++k) { sv[k] = sc[lane + 32 * k]; m = fmaxf(m, sv[k]); }
        #pragma unroll
        for (int off = 16; off > 0; off >>= 1)
            m = fmaxf(m, __shfl_xor_sync(0xffffffffu, m, off));
        float ssum = 0.f, acc[8];
        #pragma unroll
        for (int d = 0; d < 8; ++d) acc[d] = 0.f;
        #pragma unroll
        for (int k = 0; k < 8; ++k) {
            float e = __expf(sv[k] - m);
            ssum += e;
            int n = half * 256 + lane + 32 * k;
            #pragma unroll
            for (int d = 0; d < 8; ++d) acc[d] = fmaf(e, s->vT[d * NSEQ + n], acc[d]);
        }
        #pragma unroll
        for (int off = 16; off > 0; off >>= 1) {
            ssum += __shfl_xor_sync(0xffffffffu, ssum, off);
            #pragma unroll
            for (int d = 0; d < 8; ++d) acc[d] += __shfl_xor_sync(0xffffffffu, acc[d], off);
        }
        if (lane == 0) {
            s->mpart[wid] = m;
            s->spart[wid] = ssum;
            #pragma unroll
            for (int d = 0; d < 8; ++d) s->opart[wid][d] = acc[d];
        }
    }
    __syncthreads();

    // ovec combine (exact two-way softmax merge)
    if (tid < 64) {
        int h = tid >> 3, d = tid & 7;
        float m0 = s->mpart[2 * h], m1 = s->mpart[2 * h + 1];
        float m = fmaxf(m0, m1);
        float e0 = __expf(m0 - m), e1 = __expf(m1 - m);
        float ss = s->spart[2 * h] * e0 + s->spart[2 * h + 1] * e1;
        float ov = s->opart[2 * h][d] * e0 + s->opart[2 * h + 1][d] * e1;
        s->ovec[8 * h + d] = ov / ss;
    }
    __syncthreads();

    // ---------------- fold ovec*Wo -> B-frag-native layout in scores area ----------------
    {
        float* wof = s->scores;
        #pragma unroll
        for (int i = 0; i < 8; ++i) {
            int idx = tid + i * NT;
            int j = idx >> 6, n = idx & 63;     // Wo row j (k-dim), col n
            wof[wpos8(j, n)] = rna(s->wo[j * 64 + n] * s->ovec[j]);
        }
    }
    __syncthreads();

    // ---------------- pass B: out = G @ Wo' + bo (tensor cores) ----------------
    {
        const float* wof = s->scores;
        float dB[2][8][4];
        #pragma unroll
        for (int mt = 0; mt < 2; ++mt)
            #pragma unroll
            for (int nt = 0; nt < 8; ++nt)
                #pragma unroll
                for (int q = 0; q < 4; ++q) dB[mt][nt][q] = 0.f;

        #pragma unroll
        for (int mt = 0; mt < 2; ++mt) {
            const int mtile = 2 * wid + mt;
            #pragma unroll
            for (int ks = 0; ks < 8; ++ks) {
                float4 af = *reinterpret_cast<const float4*>(
                    s->xb + (mtile * 8 + ks) * 128 + lane * 4);
                const float* wb = wof + (ks * 8) * 64 + lane * 2;
                #pragma unroll
                for (int nt = 0; nt < 8; ++nt) {
                    float2 bf = *reinterpret_cast<const float2*>(wb + nt * 64);
                    mma_tf32(dB[mt][nt], af, bf);
                }
            }
        }

        float boA[8], boB[8];
        #pragma unroll
        for (int nt = 0; nt < 8; ++nt) {
            boA[nt] = s->bov[nt * 8 + cfrag];
            boB[nt] = s->bov[nt * 8 + cfrag + 1];
        }
        #pragma unroll
        for (int mt = 0; mt < 2; ++mt) {
            const int mtile = 2 * wid + mt;
            const int rA = mtile * 16 + rfrag, rB = rA + 8;
            float* opA = out + ((size_t)rA * LRES + l) * 64;
            float* opB = out + ((size_t)rB * LRES + l) * 64;
            #pragma unroll
            for (int nt = 0; nt < 8; ++nt) {
                int colA = nt * 8 + cfrag;
                float2 oa = make_float2(dB[mt][nt][0] + boA[nt], dB[mt][nt][1] + boB[nt]);
                float2 ob = make_float2(dB[mt][nt][2] + boA[nt], dB[mt][nt][3] + boB[nt]);
                *reinterpret_cast<float2*>(opA + colA) = oa;
                *reinterpret_cast<float2*>(opB + colA) = ob;
            }
        }
    }
}

extern "C" void kernel_launch(void* const* d_in, const int* in_sizes, int n_in,
                              void* d_out, int out_size) {
    const float* msa = (const float*)d_in[0];
    const float* lnw = (const float*)d_in[1];
    const float* lnb = (const float*)d_in[2];
    const float* wq  = (const float*)d_in[3];
    const float* wk  = (const float*)d_in[4];
    const float* wv  = (const float*)d_in[5];
    const float* wg  = (const float*)d_in[6];
    const float* bg  = (const float*)d_in[7];
    const float* wo  = (const float*)d_in[8];
    const float* bo  = (const float*)d_in[9];
    float* out = (float*)d_out;

    const int smem_bytes = (int)sizeof(Smem);
    cudaFuncSetAttribute(msa_col_attn_v17,
                         cudaFuncAttributeMaxDynamicSharedMemorySize, smem_bytes);
    msa_col_attn_v17<<<LRES, NT, smem_bytes>>>(
        msa, lnw, lnb, wq, wk, wv, wg, bg, wo, bo, out);
}